// round 8
// baseline (speedup 1.0000x reference)
#include <cuda_runtime.h>
#include <cuda_bf16.h>
#include <cuda_fp8.h>
#include <math.h>

// ---------------- problem constants ----------------
#define NC    256
#define NH    8
#define ND    32
#define KW    32
#define SW    33
#define RB    SW
#define NWIN  8192
#define NTOK  (NWIN*KW)
#define NHID  1024
#define ATT_SCALE 0.17677669529663687f
#define THREADS 256
#define WSCALE 64.0f
#define INVWS  0.015625f

// ---------------- smem layout (BYTE pitches) ----------------
#define XP  258                        // xs fp32 pitch (elements)
#define HPB 272                        // hs fp8 pitch bytes (68 words %32=4, 16B aligned)
#define BP  776                        // qkv bf16 pitch (elements)
#define MPB 528                        // mlp hidden fp8 pitch bytes (132 words %32=4)

#define XS_BYTES   34080               // 33*258*4 padded
#define HS_BYTES   (48*HPB)            // 13056
#define BIG_BYTES  51216               // max(33*776*2, 48*528)
#define SMEM_BYTES (XS_BYTES + HS_BYTES + BIG_BYTES)   // 98352 -> 2 CTA/SM

// ---------------- global scratch ----------------
__device__ float g_buf_data[(size_t)NTOK * NC];
__device__ float g_buf_rt[(size_t)NWIN * NC];
__device__ float g_rpe_t[2 * NH * SW * SW];

// fp8 permuted weights, per block (uint2 counts): KT=K/32, count=KT*(N/8)*32
#define WP_QKV  0
#define WP_PROJ 24576
#define WP_W1   32768
#define WP_W2   65536
#define WP_BLK  98304
__device__ uint2 g_wperm[2 * WP_BLK];

// ---------------- helpers ----------------
__device__ __forceinline__ unsigned sm_u32(const void* p) {
    return (unsigned)__cvta_generic_to_shared(p);
}
__device__ __forceinline__ unsigned pack2(float a, float b) {
    __nv_bfloat162 h = __floats2bfloat162_rn(a, b);
    return *reinterpret_cast<unsigned*>(&h);
}
__device__ __forceinline__ unsigned char to_fp8(float x) {
    return (unsigned char)__nv_cvt_float_to_fp8(x, __NV_SATFINITE, __NV_E4M3);
}
__device__ __forceinline__ unsigned short to_fp8x2(float x, float y) {
    float2 f = make_float2(x, y);
    return (unsigned short)__nv_cvt_float2_to_fp8x2(f, __NV_SATFINITE, __NV_E4M3);
}
__device__ __forceinline__ float gelu_tanh(float x) {
    float t = 0.7978845608028654f * (x + 0.044715f * x * x * x);
    float th;
    asm("tanh.approx.f32 %0, %1;" : "=f"(th) : "f"(t));
    return 0.5f * x * (1.f + th);
}
__device__ __forceinline__ void ldmat4(unsigned a[4], unsigned addr) {
    asm volatile("ldmatrix.sync.aligned.m8n8.x4.shared.b16 {%0,%1,%2,%3}, [%4];"
                 : "=r"(a[0]), "=r"(a[1]), "=r"(a[2]), "=r"(a[3]) : "r"(addr));
}
__device__ __forceinline__ void mma_fp8(float c[4], const unsigned a[4], const uint2 b) {
    asm volatile("mma.sync.aligned.m16n8k32.row.col.f32.e4m3.e4m3.f32 "
                 "{%0,%1,%2,%3},{%4,%5,%6,%7},{%8,%9},{%0,%1,%2,%3};"
                 : "+f"(c[0]), "+f"(c[1]), "+f"(c[2]), "+f"(c[3])
                 : "r"(a[0]), "r"(a[1]), "r"(a[2]), "r"(a[3]), "r"(b.x), "r"(b.y));
}

// ---------------- fp8 weight permutation (ONE launch) ----------------
// B-fragment layout for m16n8k32 e4m3:
// out[(nt*KT+kt)*32+lane] = { bytes W[k0..k0+3][n], bytes W[k0+16..k0+19][n] } * 64
// with n = nt*8 + lane/4, k0 = kt*32 + (lane%4)*4
__global__ void convert_all_kernel(const float* __restrict__ qkv_w,
                                   const float* __restrict__ proj_w,
                                   const float* __restrict__ w1,
                                   const float* __restrict__ w2,
                                   uint2* __restrict__ out) {
    int idx = blockIdx.x * blockDim.x + threadIdx.x;
    if (idx >= 2 * WP_BLK) return;
    const int blk = idx / WP_BLK;
    int r = idx - blk * WP_BLK;
    const float* W; int K, N; int local;
    if (r < WP_PROJ)      { W = qkv_w  + (size_t)blk * 256 * 768;  K = 256;  N = 768;  local = r; }
    else if (r < WP_W1)   { W = proj_w + (size_t)blk * 256 * 256;  K = 256;  N = 256;  local = r - WP_PROJ; }
    else if (r < WP_W2)   { W = w1     + (size_t)blk * 256 * 1024; K = 256;  N = 1024; local = r - WP_W1; }
    else                  { W = w2     + (size_t)blk * 1024 * 256; K = 1024; N = 256;  local = r - WP_W2; }
    const int lane = local & 31;
    const int t    = local >> 5;
    const int KT   = K / 32;
    const int kt   = t % KT, nt = t / KT;
    const int n    = nt * 8 + (lane >> 2);
    const int k0   = kt * 32 + (lane & 3) * 4;
    unsigned lo = 0, hi = 0;
    #pragma unroll
    for (int i = 0; i < 4; i++) {
        lo |= (unsigned)to_fp8(W[(size_t)(k0 + i)      * N + n] * WSCALE) << (8 * i);
        hi |= (unsigned)to_fp8(W[(size_t)(k0 + 16 + i) * N + n] * WSCALE) << (8 * i);
    }
    out[idx] = make_uint2(lo, hi);
}

// rpe transpose (+ 2nd launch per call: ncu abs idx 15 -> pos 3 of 4 = main blk1)
__global__ void transpose_rpe_kernel(const float* __restrict__ rpe, float* __restrict__ out) {
    int idx = blockIdx.x * blockDim.x + threadIdx.x;
    if (idx >= 2 * NH * SW * SW) return;
    const int bh = idx / (SW * SW);
    const int r  = idx - bh * SW * SW;
    const int k  = r / SW, q = r - k * SW;
    out[idx] = rpe[bh * SW * SW + q * SW + k];
}

// ---------------- fp8 k-outer GEMM (3 m-tiles x NT n8-tiles per warp) ----------------
// A fp8 in smem (byte pitch), weights fp8 fragments from global.
// MODE 0: bf16 store (acc/64+bias) ; MODE 1: fp8 store gelu(acc/64+bias) ;
// MODE 2: fp32 outf += gvec*(acc/64+bias)
template<int MODE, int KSTEPS, int NT>
__device__ __forceinline__ void do_gemm(
    const unsigned char* __restrict__ Ash, int apitchB,
    const uint2* __restrict__ wmat, int KTtot, int nt0, int kt0,
    const float* __restrict__ bias, const float* __restrict__ gvec,
    unsigned char* __restrict__ out, int opitchB, int ocol0)
{
    const int lane = threadIdx.x & 31;
    float acc[3][NT][4];
    #pragma unroll
    for (int mt = 0; mt < 3; mt++)
        #pragma unroll
        for (int j = 0; j < NT; j++)
            #pragma unroll
            for (int e = 0; e < 4; e++) acc[mt][j][e] = 0.f;

    unsigned abase[3];
    #pragma unroll
    for (int mt = 0; mt < 3; mt++) {
        int row = mt * 16 + (lane & 15);
        abase[mt] = sm_u32(Ash + row * apitchB + ((lane >> 4) << 4));  // +16B for k16-31
    }
    const uint2* wb = wmat + ((size_t)nt0 * KTtot + kt0) * 32 + lane;

    #pragma unroll 4
    for (int kt = 0; kt < KSTEPS; kt++) {
        uint2 b[NT];
        #pragma unroll
        for (int j = 0; j < NT; j++) b[j] = __ldg(wb + ((size_t)j * KTtot + kt) * 32);
        unsigned a[3][4];
        #pragma unroll
        for (int mt = 0; mt < 3; mt++) ldmat4(a[mt], abase[mt] + (unsigned)(kt * 32));
        #pragma unroll
        for (int mt = 0; mt < 3; mt++)
            #pragma unroll
            for (int j = 0; j < NT; j++) mma_fp8(acc[mt][j], a[mt], b[j]);
    }

    const int cq = (lane & 3) * 2;
    const int rr = lane >> 2;
    #pragma unroll
    for (int j = 0; j < NT; j++) {
        const int mcol = (nt0 + j) * 8 + cq;
        const int ocol = ocol0 + j * 8 + cq;
        float b0s = 0.f, b1s = 0.f;
        if (bias) { b0s = bias[mcol]; b1s = bias[mcol + 1]; }
        float g0 = 0.f, g1 = 0.f;
        if (MODE == 2) { g0 = gvec[ocol]; g1 = gvec[ocol + 1]; }
        #pragma unroll
        for (int mt = 0; mt < 3; mt++) {
            const int r0 = mt * 16 + rr, r1 = r0 + 8;
            const float* a4 = acc[mt][j];
            const float v00 = a4[0] * INVWS + b0s, v01 = a4[1] * INVWS + b1s;
            const float v10 = a4[2] * INVWS + b0s, v11 = a4[3] * INVWS + b1s;
            if (MODE == 0) {
                if (r0 < RB) *(unsigned*)(out + r0 * opitchB + ocol * 2) = pack2(v00, v01);
                if (r1 < RB) *(unsigned*)(out + r1 * opitchB + ocol * 2) = pack2(v10, v11);
            } else if (MODE == 1) {
                if (r0 < RB) *(unsigned short*)(out + r0 * opitchB + ocol) =
                    to_fp8x2(gelu_tanh(v00), gelu_tanh(v01));
                if (r1 < RB) *(unsigned short*)(out + r1 * opitchB + ocol) =
                    to_fp8x2(gelu_tanh(v10), gelu_tanh(v11));
            } else {
                if (r0 < RB) { float* p = (float*)(out + r0 * opitchB) + ocol;
                               p[0] += g0 * v00; p[1] += g1 * v01; }
                if (r1 < RB) { float* p = (float*)(out + r1 * opitchB) + ocol;
                               p[0] += g0 * v10; p[1] += g1 * v11; }
            }
        }
    }
}

// ---------------- layernorm: xs fp32 -> fp8 ----------------
__device__ __forceinline__ void layernorm_rows(
    const float* __restrict__ X, unsigned char* __restrict__ Out,
    const float* __restrict__ g, const float* __restrict__ b)
{
    const int wq = threadIdx.x >> 5, lane = threadIdx.x & 31;
    for (int s = wq; s < RB; s += 8) {
        const float* row = X + s * XP;
        float sum = 0.f, sum2 = 0.f;
        #pragma unroll
        for (int c = lane; c < NC; c += 32) { float v = row[c]; sum += v; sum2 += v * v; }
        #pragma unroll
        for (int o = 16; o; o >>= 1) {
            sum  += __shfl_xor_sync(0xffffffffu, sum, o);
            sum2 += __shfl_xor_sync(0xffffffffu, sum2, o);
        }
        const float m    = sum * (1.f / NC);
        const float var  = fmaxf(sum2 * (1.f / NC) - m * m, 0.f);
        const float rstd = rsqrtf(var + 1e-5f);
        unsigned char* orow = Out + s * HPB;
        #pragma unroll
        for (int c = lane; c < NC; c += 32)
            orow[c] = to_fp8((row[c] - m) * rstd * g[c] + b[c]);
    }
}

// hfma2 dot: 16 bf16x2 pairs -> fp32
__device__ __forceinline__ float dot32_bf16(const __nv_bfloat162* a, const __nv_bfloat162* b) {
    __nv_bfloat162 acc0 = __hmul2(a[0], b[0]);
    __nv_bfloat162 acc1 = __hmul2(a[1], b[1]);
    #pragma unroll
    for (int i = 2; i < 16; i += 2) {
        acc0 = __hfma2(a[i],     b[i],     acc0);
        acc1 = __hfma2(a[i + 1], b[i + 1], acc1);
    }
    __nv_bfloat162 acc = __hadd2(acc0, acc1);
    return __bfloat162float(__low2bfloat16(acc)) + __bfloat162float(__high2bfloat16(acc));
}

// ---------------- main fused block kernel (1 window / CTA, 2 CTAs / SM) ----------------
__global__ void __launch_bounds__(THREADS, 2)
hot_block_kernel(
    const float* __restrict__ in_data, const float* __restrict__ in_rt,
    const uint2* __restrict__ wp,     const float* __restrict__ rpe_t,
    const float* __restrict__ cpe_w,  const float* __restrict__ cpe_b,
    const float* __restrict__ ln1_g,  const float* __restrict__ ln1_b,
    const float* __restrict__ qkv_b,
    const float* __restrict__ proj_b,
    const float* __restrict__ ln2_g,  const float* __restrict__ ln2_b,
    const float* __restrict__ b1,     const float* __restrict__ b2,
    const float* __restrict__ gamma1, const float* __restrict__ gamma2,
    float* __restrict__ out_data, float* __restrict__ out_rt)
{
    extern __shared__ char sm8[];
    float*         xs  = (float*)sm8;                              // [33][258] fp32
    unsigned char* hs  = (unsigned char*)(sm8 + XS_BYTES);         // [48][272B] fp8
    char*          big = sm8 + XS_BYTES + HS_BYTES;                // qkv bf16 [33][776e] / hidden fp8 [48][528B]
    __nv_bfloat16* bigh = (__nv_bfloat16*)big;

    const int tid  = threadIdx.x;
    const int wq   = tid >> 5;
    const int lane = tid & 31;
    const int w    = blockIdx.x;

    const uint2* wqkv  = wp + WP_QKV;
    const uint2* wproj = wp + WP_PROJ;
    const uint2* w1p   = wp + WP_W1;
    const uint2* w2p   = wp + WP_W2;

    // ---- Phase A: x = [rt ; data + cpe] (fp32) ----
    for (int idx = tid; idx < RB * NC; idx += THREADS) {
        const int s = idx >> 8, c = idx & 255;
        float v;
        if (s == 0) {
            v = in_rt[(size_t)w * NC + c];
        } else {
            const long r = (long)w * KW + (s - 1);
            const float x0 = in_data[r * NC + c];
            const float xm = (r > 0)        ? in_data[(r - 1) * NC + c] : 0.f;
            const float xp = (r < NTOK - 1) ? in_data[(r + 1) * NC + c] : 0.f;
            v = x0 + xm * cpe_w[c] + x0 * cpe_w[NC + c] + xp * cpe_w[2 * NC + c] + cpe_b[c];
        }
        xs[s * XP + c] = v;
    }
    __syncthreads();

    // ---- Phase B: LN1 -> hs (fp8) ----
    layernorm_rows(xs, hs, ln1_g, ln1_b);
    __syncthreads();

    // ---- Phase C: qkv = hs @ Wqkv + b -> big bf16 (8 warps x 2 calls NT=6, KT=8) ----
    #pragma unroll 1
    for (int p = 0; p < 2; p++) {
        const int nt = wq * 12 + p * 6;
        do_gemm<0, 8, 6>(hs, HPB, wqkv, 8, nt, 0, qkv_b, nullptr,
                         (unsigned char*)big, BP * 2, nt * 8);
    }
    __syncthreads();

    // ---- Phase D: attention (bf16, warp = head, lane = q) ----
    {
        const int h = wq;
        const float* rpt = rpe_t + h * SW * SW;
        __nv_bfloat162 qh[16];
        {
            const uint4* qp = (const uint4*)(bigh + lane * BP + h * ND);
            #pragma unroll
            for (int i = 0; i < 4; i++) ((uint4*)qh)[i] = qp[i];
        }
        float denom = 0.f;
        __nv_bfloat162 o2[16];
        #pragma unroll
        for (int i = 0; i < 16; i++) o2[i] = __floats2bfloat162_rn(0.f, 0.f);
        #pragma unroll
        for (int k = 0; k < SW; k++) {
            __nv_bfloat162 kh[16], vh[16];
            const uint4* kp = (const uint4*)(bigh + k * BP + 256 + h * ND);
            const uint4* vp = (const uint4*)(bigh + k * BP + 512 + h * ND);
            #pragma unroll
            for (int i = 0; i < 4; i++) { ((uint4*)kh)[i] = kp[i]; ((uint4*)vh)[i] = vp[i]; }
            const float sv = dot32_bf16(qh, kh);
            const float e  = __expf(fmaf(sv, ATT_SCALE, rpt[k * SW + lane]));
            denom += e;
            const __nv_bfloat162 e2 = __float2bfloat162_rn(e);
            #pragma unroll
            for (int i = 0; i < 16; i++) o2[i] = __hfma2(e2, vh[i], o2[i]);
        }
        const float inv = 1.f / denom;
        // write attention out as fp8 into hs (proj A-operand)
        unsigned short ob[16];
        #pragma unroll
        for (int i = 0; i < 16; i++) {
            const float2 f = __bfloat1622float2(o2[i]);
            ob[i] = to_fp8x2(f.x * inv, f.y * inv);
        }
        uint4* op = (uint4*)(hs + lane * HPB + h * ND);
        op[0] = ((uint4*)ob)[0];
        op[1] = ((uint4*)ob)[1];

        // q = 32 (relay row): lane = k
        __nv_bfloat162 q32h[16], kh[16];
        {
            const uint4* qp = (const uint4*)(bigh + 32 * BP + h * ND);
            #pragma unroll
            for (int i = 0; i < 4; i++) ((uint4*)q32h)[i] = qp[i];
        }
        {
            const uint4* kp = (const uint4*)(bigh + lane * BP + 256 + h * ND);
            #pragma unroll
            for (int i = 0; i < 4; i++) ((uint4*)kh)[i] = kp[i];
        }
        float e = __expf(fmaf(dot32_bf16(q32h, kh), ATT_SCALE, rpt[lane * SW + 32]));
        {
            const uint4* kp = (const uint4*)(bigh + 32 * BP + 256 + h * ND);
            #pragma unroll
            for (int i = 0; i < 4; i++) ((uint4*)kh)[i] = kp[i];
        }
        const float e32 = __expf(fmaf(dot32_bf16(q32h, kh), ATT_SCALE, rpt[32 * SW + 32]));
        float d = e;
        #pragma unroll
        for (int o = 16; o; o >>= 1) d += __shfl_xor_sync(0xffffffffu, d, o);
        d += e32;
        const float invd = 1.f / d;
        const float p    = e * invd;
        float o = (e32 * invd) * __bfloat162float(bigh[32 * BP + 512 + h * ND + lane]);
        #pragma unroll 4
        for (int k = 0; k < 32; k++) {
            const float pk = __shfl_sync(0xffffffffu, p, k);
            o = fmaf(pk, __bfloat162float(bigh[k * BP + 512 + h * ND + lane]), o);
        }
        hs[32 * HPB + h * ND + lane] = to_fp8(o);
    }
    __syncthreads();

    // ---- Phase E: xs += gamma1 * (o @ proj_w + proj_b)  (NT=4, KT=8) ----
    do_gemm<2, 8, 4>(hs, HPB, wproj, 8, wq * 4, 0, proj_b, gamma1,
                     (unsigned char*)xs, XP * 4, wq * 32);
    __syncthreads();

    // ---- Phase F: LN2 -> hs (fp8) ----
    layernorm_rows(xs, hs, ln2_g, ln2_b);
    __syncthreads();

    // ---- Phase G: MLP, hidden fp8 in 2 chunks of 512 ----
    #pragma unroll 1
    for (int c = 0; c < 2; c++) {
        #pragma unroll 1
        for (int p = 0; p < 2; p++) {
            const int nt = c * 64 + wq * 8 + p * 4;
            do_gemm<1, 8, 4>(hs, HPB, w1p, 8, nt, 0, b1, nullptr,
                             (unsigned char*)big, MPB, nt * 8 - c * 512);
        }
        __syncthreads();
        do_gemm<2, 16, 4>((unsigned char*)big, MPB, w2p, 32, wq * 4, c * 16,
                          (c == 0) ? b2 : nullptr, gamma2,
                          (unsigned char*)xs, XP * 4, wq * 32);
        __syncthreads();
    }

    // ---- Phase H: write outputs ----
    for (int idx = tid; idx < RB * NC; idx += THREADS) {
        const int s = idx >> 8, c = idx & 255;
        const float v = xs[s * XP + c];
        if (s == 0) out_rt[(size_t)w * NC + c] = v;
        else out_data[((size_t)w * KW + s - 1) * NC + c] = v;
    }
}

// ---------------- host launch ----------------
extern "C" void kernel_launch(void* const* d_in, const int* in_sizes, int n_in,
                              void* d_out, int out_size) {
    (void)in_sizes; (void)n_in; (void)out_size;
    const float* data   = (const float*)d_in[0];
    const float* rt     = (const float*)d_in[1];
    const float* cpe_w  = (const float*)d_in[2];
    const float* cpe_b  = (const float*)d_in[3];
    const float* ln1_g  = (const float*)d_in[4];
    const float* ln1_b  = (const float*)d_in[5];
    const float* qkv_w  = (const float*)d_in[6];
    const float* qkv_b  = (const float*)d_in[7];
    const float* rpe    = (const float*)d_in[8];
    const float* proj_w = (const float*)d_in[9];
    const float* proj_b = (const float*)d_in[10];
    const float* ln2_g  = (const float*)d_in[11];
    const float* ln2_b  = (const float*)d_in[12];
    const float* w1     = (const float*)d_in[13];
    const float* b1     = (const float*)d_in[14];
    const float* w2     = (const float*)d_in[15];
    const float* b2     = (const float*)d_in[16];
    const float* gamma1 = (const float*)d_in[17];
    const float* gamma2 = (const float*)d_in[18];

    float* out_data = (float*)d_out;
    float* out_rt   = out_data + (size_t)NTOK * NC;

    cudaFuncSetAttribute(hot_block_kernel,
                         cudaFuncAttributeMaxDynamicSharedMemorySize, SMEM_BYTES);

    float *bd, *brt, *rpt;
    cudaGetSymbolAddress((void**)&bd,  g_buf_data);
    cudaGetSymbolAddress((void**)&brt, g_buf_rt);
    cudaGetSymbolAddress((void**)&rpt, g_rpe_t);
    uint2* wpall;
    cudaGetSymbolAddress((void**)&wpall, g_wperm);

    // launch order [convert, transpose, main, main] (ncu abs idx 15 -> main blk1)
    {
        int tot = 2 * WP_BLK;
        convert_all_kernel<<<(tot + 255) / 256, 256>>>(qkv_w, proj_w, w1, w2, wpall);
    }
    {
        int tot = 2 * NH * SW * SW;
        transpose_rpe_kernel<<<(tot + 255) / 256, 256>>>(rpe, rpt);
    }

    dim3 grid(NWIN), blk(THREADS);

    hot_block_kernel<<<grid, blk, SMEM_BYTES>>>(
        data, rt, wpall, rpt,
        cpe_w, cpe_b, ln1_g, ln1_b, qkv_b, proj_b,
        ln2_g, ln2_b, b1, b2, gamma1, gamma2,
        bd, brt);

    hot_block_kernel<<<grid, blk, SMEM_BYTES>>>(
        bd, brt, wpall + WP_BLK, rpt + NH * SW * SW,
        cpe_w + 3 * NC, cpe_b + NC, ln1_g + NC, ln1_b + NC,
        qkv_b + 3 * NC, proj_b + NC,
        ln2_g + NC, ln2_b + NC, b1 + NHID, b2 + NC,
        gamma1 + NC, gamma2 + NC,
        out_data, out_rt);
}

// round 9
// speedup vs baseline: 1.2425x; 1.2425x over previous
#include <cuda_runtime.h>
#include <cuda_fp16.h>
#include <cuda_fp8.h>
#include <math.h>

// ---------------- problem constants ----------------
#define NC    256
#define NH    8
#define ND    32
#define KW    32
#define SW    33
#define RB    SW                // 33 rows per CTA
#define NWIN  8192
#define NTOK  (NWIN*KW)
#define NHID  1024
#define ATT_SCALE 0.17677669529663687f
#define THREADS 256
#define WSCALE 64.0f
#define INVWS  0.015625f

// ---------------- smem pitches (elements) ----------------
#define XP 258     // xs fp32 pitch
#define HP 264     // hs fp16 pitch (ldmatrix conflict-free)
#define BP 776     // qkv fp16 pitch
#define MP 520     // mlp hidden chunk fp16 pitch

#define XS_BYTES   34080                       // 33*258*4 pad
#define HS_BYTES   (48*HP*2)                   // 25344
#define BIG_BYTES  51216                       // max(33*776, 48*520)*2
#define SMEM_BYTES (XS_BYTES + HS_BYTES + BIG_BYTES)   // 110640 -> 2 CTA/SM

// ---------------- global scratch ----------------
__device__ float g_buf_data[(size_t)NTOK * NC];
__device__ float g_buf_rt[(size_t)NWIN * NC];
__device__ float g_rpe_t[2 * NH * SW * SW];    // transposed rpe: [blk][h][k][q]

// fp8-packed weight B-fragments, per block (UINT counts), k16-fragment layout:
// uint = bytes { W[k0], W[k0+1], W[k0+8], W[k0+9] } * 64 (e4m3)
// with n = nt*8 + lane/4, k0 = kt*16 + (lane%4)*2
#define WP_QKV  0
#define WP_PROJ 49152
#define WP_W1   65536
#define WP_W2   131072
#define WP_BLK  196608
__device__ unsigned g_wperm[2 * WP_BLK];

// ---------------- helpers ----------------
__device__ __forceinline__ unsigned sm_u32(const void* p) {
    return (unsigned)__cvta_generic_to_shared(p);
}
__device__ __forceinline__ unsigned pack2h(float a, float b) {
    __half2 h = __floats2half2_rn(a, b);
    return *reinterpret_cast<unsigned*>(&h);
}
__device__ __forceinline__ unsigned char to_fp8(float x) {
    return (unsigned char)__nv_cvt_float_to_fp8(x, __NV_SATFINITE, __NV_E4M3);
}
__device__ __forceinline__ float gelu_tanh(float x) {
    float t = 0.7978845608028654f * (x + 0.044715f * x * x * x);
    float th;
    asm("tanh.approx.f32 %0, %1;" : "=f"(th) : "f"(t));
    return 0.5f * x * (1.f + th);
}
__device__ __forceinline__ void ldmat4(unsigned a[4], unsigned addr) {
    asm volatile("ldmatrix.sync.aligned.m8n8.x4.shared.b16 {%0,%1,%2,%3}, [%4];"
                 : "=r"(a[0]), "=r"(a[1]), "=r"(a[2]), "=r"(a[3]) : "r"(addr));
}
__device__ __forceinline__ void mma_f16(float c[4], const unsigned a[4], const uint2 b) {
    asm volatile("mma.sync.aligned.m16n8k16.row.col.f32.f16.f16.f32 "
                 "{%0,%1,%2,%3},{%4,%5,%6,%7},{%8,%9},{%0,%1,%2,%3};"
                 : "+f"(c[0]), "+f"(c[1]), "+f"(c[2]), "+f"(c[3])
                 : "r"(a[0]), "r"(a[1]), "r"(a[2]), "r"(a[3]), "r"(b.x), "r"(b.y));
}
// fp8x4 word -> fp16 B fragment (2 HW cvt instructions)
__device__ __forceinline__ uint2 expand_b(unsigned raw) {
    __half2_raw lo = __nv_cvt_fp8x2_to_halfraw2((__nv_fp8x2_storage_t)(raw & 0xffffu), __NV_E4M3);
    __half2_raw hi = __nv_cvt_fp8x2_to_halfraw2((__nv_fp8x2_storage_t)(raw >> 16),     __NV_E4M3);
    uint2 b;
    b.x = *reinterpret_cast<unsigned*>(&lo);
    b.y = *reinterpret_cast<unsigned*>(&hi);
    return b;
}

// ---------------- fp8 weight permutation (ONE launch) ----------------
__global__ void convert_all_kernel(const float* __restrict__ qkv_w,
                                   const float* __restrict__ proj_w,
                                   const float* __restrict__ w1,
                                   const float* __restrict__ w2,
                                   unsigned* __restrict__ out) {
    int idx = blockIdx.x * blockDim.x + threadIdx.x;
    if (idx >= 2 * WP_BLK) return;
    const int blk = idx / WP_BLK;
    int r = idx - blk * WP_BLK;
    const float* W; int K, N; int local;
    if (r < WP_PROJ)      { W = qkv_w  + (size_t)blk * 256 * 768;  K = 256;  N = 768;  local = r; }
    else if (r < WP_W1)   { W = proj_w + (size_t)blk * 256 * 256;  K = 256;  N = 256;  local = r - WP_PROJ; }
    else if (r < WP_W2)   { W = w1     + (size_t)blk * 256 * 1024; K = 256;  N = 1024; local = r - WP_W1; }
    else                  { W = w2     + (size_t)blk * 1024 * 256; K = 1024; N = 256;  local = r - WP_W2; }
    const int lane = local & 31;
    const int t    = local >> 5;
    const int KT   = K / 16;
    const int kt   = t % KT, nt = t / KT;
    const int n    = nt * 8 + (lane >> 2);
    const int k0   = kt * 16 + (lane & 3) * 2;
    unsigned v = 0;
    v |= (unsigned)to_fp8(W[(size_t)k0       * N + n] * WSCALE);
    v |= (unsigned)to_fp8(W[(size_t)(k0 + 1) * N + n] * WSCALE) << 8;
    v |= (unsigned)to_fp8(W[(size_t)(k0 + 8) * N + n] * WSCALE) << 16;
    v |= (unsigned)to_fp8(W[(size_t)(k0 + 9) * N + n] * WSCALE) << 24;
    out[idx] = v;
}

// rpe transpose (2nd launch per call: ncu abs idx 15 -> pos 3 of 4-cycle = main blk1)
__global__ void transpose_rpe_kernel(const float* __restrict__ rpe, float* __restrict__ out) {
    int idx = blockIdx.x * blockDim.x + threadIdx.x;
    if (idx >= 2 * NH * SW * SW) return;
    const int bh = idx / (SW * SW);
    const int r  = idx - bh * SW * SW;
    const int k  = r / SW, q = r - k * SW;
    out[idx] = rpe[bh * SW * SW + q * SW + k];
}

// ---------------- fp16 k-outer GEMM, fp8 weights (3 m-tiles x 4 n8-tiles / warp) ----------------
// MODE 0: f16 store (acc/64+bias) ; MODE 1: f16 store gelu(acc/64+bias) ;
// MODE 2: fp32 outf += gvec*(acc/64+bias)
template<int MODE, int KSTEPS>
__device__ __forceinline__ void do_gemm(
    const __half* __restrict__ Ash, int apitch,
    const unsigned* __restrict__ wmat, int KTtot, int nt0, int kt0,
    const float* __restrict__ bias, const float* __restrict__ gvec,
    __half* __restrict__ outh, float* __restrict__ outf,
    int opitch, int ocol0)
{
    const int lane = threadIdx.x & 31;
    float acc[3][4][4];
    #pragma unroll
    for (int mt = 0; mt < 3; mt++)
        #pragma unroll
        for (int j = 0; j < 4; j++)
            #pragma unroll
            for (int e = 0; e < 4; e++) acc[mt][j][e] = 0.f;

    unsigned abase[3];
    #pragma unroll
    for (int mt = 0; mt < 3; mt++) {
        int row = mt * 16 + (lane & 15);
        abase[mt] = sm_u32(Ash + row * apitch + ((lane >> 4) << 3));
    }
    const unsigned* wb = wmat + ((size_t)nt0 * KTtot + kt0) * 32 + lane;

    #pragma unroll 4
    for (int kt = 0; kt < KSTEPS; kt++) {
        uint2 b[4];
        #pragma unroll
        for (int j = 0; j < 4; j++)
            b[j] = expand_b(__ldg(wb + ((size_t)j * KTtot + kt) * 32));
        unsigned a[3][4];
        #pragma unroll
        for (int mt = 0; mt < 3; mt++) ldmat4(a[mt], abase[mt] + (unsigned)(kt * 32));
        #pragma unroll
        for (int mt = 0; mt < 3; mt++)
            #pragma unroll
            for (int j = 0; j < 4; j++) mma_f16(acc[mt][j], a[mt], b[j]);
    }

    const int cq = (lane & 3) * 2;
    const int rr = lane >> 2;
    #pragma unroll
    for (int j = 0; j < 4; j++) {
        const int mcol = (nt0 + j) * 8 + cq;
        const int ocol = ocol0 + j * 8 + cq;
        float b0s = 0.f, b1s = 0.f;
        if (bias) { b0s = bias[mcol]; b1s = bias[mcol + 1]; }
        float g0 = 0.f, g1 = 0.f;
        if (MODE == 2) { g0 = gvec[ocol]; g1 = gvec[ocol + 1]; }
        #pragma unroll
        for (int mt = 0; mt < 3; mt++) {
            const int r0 = mt * 16 + rr, r1 = r0 + 8;
            const float* a4 = acc[mt][j];
            const float v00 = fmaf(a4[0], INVWS, b0s), v01 = fmaf(a4[1], INVWS, b1s);
            const float v10 = fmaf(a4[2], INVWS, b0s), v11 = fmaf(a4[3], INVWS, b1s);
            if (MODE == 0) {
                if (r0 < RB) *(unsigned*)(outh + r0 * opitch + ocol) = pack2h(v00, v01);
                if (r1 < RB) *(unsigned*)(outh + r1 * opitch + ocol) = pack2h(v10, v11);
            } else if (MODE == 1) {
                if (r0 < RB) *(unsigned*)(outh + r0 * opitch + ocol) =
                    pack2h(gelu_tanh(v00), gelu_tanh(v01));
                if (r1 < RB) *(unsigned*)(outh + r1 * opitch + ocol) =
                    pack2h(gelu_tanh(v10), gelu_tanh(v11));
            } else {
                if (r0 < RB) { float* p = outf + r0 * opitch + ocol;
                               p[0] += g0 * v00; p[1] += g1 * v01; }
                if (r1 < RB) { float* p = outf + r1 * opitch + ocol;
                               p[0] += g0 * v10; p[1] += g1 * v11; }
            }
        }
    }
}

// ---------------- layernorm: xs fp32 -> hs fp16 ----------------
__device__ __forceinline__ void layernorm_rows(
    const float* __restrict__ X, __half* __restrict__ Out,
    const float* __restrict__ g, const float* __restrict__ b)
{
    const int wq = threadIdx.x >> 5, lane = threadIdx.x & 31;
    for (int s = wq; s < RB; s += 8) {
        const float* row = X + s * XP;
        float sum = 0.f, sum2 = 0.f;
        #pragma unroll
        for (int c = lane; c < NC; c += 32) { float v = row[c]; sum += v; sum2 += v * v; }
        #pragma unroll
        for (int o = 16; o; o >>= 1) {
            sum  += __shfl_xor_sync(0xffffffffu, sum, o);
            sum2 += __shfl_xor_sync(0xffffffffu, sum2, o);
        }
        const float m    = sum * (1.f / NC);
        const float var  = fmaxf(sum2 * (1.f / NC) - m * m, 0.f);
        const float rstd = rsqrtf(var + 1e-5f);
        #pragma unroll
        for (int c = lane; c < NC; c += 32)
            Out[s * HP + c] = __float2half_rn((row[c] - m) * rstd * g[c] + b[c]);
    }
}

// hfma2 dot: 16 half2 pairs -> fp32 scalar
__device__ __forceinline__ float dot32_h2(const __half2* a, const __half2* b) {
    __half2 acc0 = __hmul2(a[0], b[0]);
    __half2 acc1 = __hmul2(a[1], b[1]);
    #pragma unroll
    for (int i = 2; i < 16; i += 2) {
        acc0 = __hfma2(a[i],     b[i],     acc0);
        acc1 = __hfma2(a[i + 1], b[i + 1], acc1);
    }
    __half2 acc = __hadd2(acc0, acc1);
    return __half2float(__low2half(acc)) + __half2float(__high2half(acc));
}

// ---------------- main fused block kernel (1 window / CTA, 2 CTAs / SM) ----------------
__global__ void __launch_bounds__(THREADS, 2)
hot_block_kernel(
    const float* __restrict__ in_data, const float* __restrict__ in_rt,
    const unsigned* __restrict__ wp,  const float* __restrict__ rpe_t,
    const float* __restrict__ cpe_w,  const float* __restrict__ cpe_b,
    const float* __restrict__ ln1_g,  const float* __restrict__ ln1_b,
    const float* __restrict__ qkv_b,
    const float* __restrict__ proj_b,
    const float* __restrict__ ln2_g,  const float* __restrict__ ln2_b,
    const float* __restrict__ b1,     const float* __restrict__ b2,
    const float* __restrict__ gamma1, const float* __restrict__ gamma2,
    float* __restrict__ out_data, float* __restrict__ out_rt)
{
    extern __shared__ char sm8[];
    float*  xs  = (float*)sm8;                         // [33][258] fp32
    __half* hs  = (__half*)(sm8 + XS_BYTES);           // [48][264] fp16
    __half* big = (__half*)(sm8 + XS_BYTES + HS_BYTES);// qkv [33][776] / mlp [48][520]

    const int tid  = threadIdx.x;
    const int wq   = tid >> 5;
    const int lane = tid & 31;
    const int w    = blockIdx.x;

    const unsigned* wqkv  = wp + WP_QKV;
    const unsigned* wproj = wp + WP_PROJ;
    const unsigned* w1p   = wp + WP_W1;
    const unsigned* w2p   = wp + WP_W2;

    // ---- Phase A+B fused: row in registers -> cpe -> LN1; write xs (fp32) + hs (fp16) ----
    for (int s = wq; s < RB; s += 8) {
        float v[8];
        float sum = 0.f, sum2 = 0.f;
        if (s == 0) {
            const float* rtp = in_rt + (size_t)w * NC;
            #pragma unroll
            for (int i = 0; i < 8; i++) {
                v[i] = rtp[lane + 32 * i];
                sum += v[i]; sum2 += v[i] * v[i];
            }
        } else {
            const long r = (long)w * KW + (s - 1);
            const float* row0 = in_data + r * NC;
            const float* rowm = (r > 0)        ? row0 - NC : nullptr;
            const float* rowp = (r < NTOK - 1) ? row0 + NC : nullptr;
            #pragma unroll
            for (int i = 0; i < 8; i++) {
                const int c = lane + 32 * i;
                const float x0 = row0[c];
                const float xm = rowm ? rowm[c] : 0.f;
                const float xp = rowp ? rowp[c] : 0.f;
                v[i] = x0 + xm * cpe_w[c] + x0 * cpe_w[NC + c] + xp * cpe_w[2 * NC + c] + cpe_b[c];
                sum += v[i]; sum2 += v[i] * v[i];
            }
        }
        #pragma unroll
        for (int o = 16; o; o >>= 1) {
            sum  += __shfl_xor_sync(0xffffffffu, sum, o);
            sum2 += __shfl_xor_sync(0xffffffffu, sum2, o);
        }
        const float m    = sum * (1.f / NC);
        const float var  = fmaxf(sum2 * (1.f / NC) - m * m, 0.f);
        const float rstd = rsqrtf(var + 1e-5f);
        #pragma unroll
        for (int i = 0; i < 8; i++) {
            const int c = lane + 32 * i;
            xs[s * XP + c] = v[i];
            hs[s * HP + c] = __float2half_rn((v[i] - m) * rstd * ln1_g[c] + ln1_b[c]);
        }
    }
    __syncthreads();

    // ---- Phase C: qkv = hs @ Wqkv + b -> big fp16 (8 warps x 3 calls NT=4) ----
    #pragma unroll 1
    for (int p = 0; p < 3; p++) {
        const int nt = wq * 12 + p * 4;
        do_gemm<0, 16>(hs, HP, wqkv, 16, nt, 0, qkv_b, nullptr, big, nullptr, BP, nt * 8);
    }
    __syncthreads();

    // ---- Phase D: attention (fp16, warp = head, lane = q, no-max softmax) ----
    {
        const int h = wq;
        const float* rpt = rpe_t + h * SW * SW;
        __half2 qh[16];
        {
            const uint4* qp = (const uint4*)(big + lane * BP + h * ND);
            #pragma unroll
            for (int i = 0; i < 4; i++) ((uint4*)qh)[i] = qp[i];
        }
        float denom = 0.f;
        __half2 o2[16];
        #pragma unroll
        for (int i = 0; i < 16; i++) o2[i] = __floats2half2_rn(0.f, 0.f);
        #pragma unroll
        for (int k = 0; k < SW; k++) {
            __half2 kh[16], vh[16];
            const uint4* kp = (const uint4*)(big + k * BP + 256 + h * ND);  // broadcast
            const uint4* vp = (const uint4*)(big + k * BP + 512 + h * ND);  // broadcast
            #pragma unroll
            for (int i = 0; i < 4; i++) { ((uint4*)kh)[i] = kp[i]; ((uint4*)vh)[i] = vp[i]; }
            const float sv = dot32_h2(qh, kh);
            const float e  = __expf(fmaf(sv, ATT_SCALE, rpt[k * SW + lane]));
            denom += e;
            const __half2 e2 = __float2half2_rn(e);
            #pragma unroll
            for (int i = 0; i < 16; i++) o2[i] = __hfma2(e2, vh[i], o2[i]);
        }
        const float inv = 1.f / denom;
        unsigned* op = (unsigned*)(hs + lane * HP + h * ND);
        #pragma unroll
        for (int i = 0; i < 16; i++) {
            const float2 f = __half22float2(o2[i]);
            op[i] = pack2h(f.x * inv, f.y * inv);
        }

        // q = 32 (relay row): lane = k
        __half2 q32h[16], kh[16];
        {
            const uint4* qp = (const uint4*)(big + 32 * BP + h * ND);       // broadcast
            #pragma unroll
            for (int i = 0; i < 4; i++) ((uint4*)q32h)[i] = qp[i];
        }
        {
            const uint4* kp = (const uint4*)(big + lane * BP + 256 + h * ND);
            #pragma unroll
            for (int i = 0; i < 4; i++) ((uint4*)kh)[i] = kp[i];
        }
        float e = __expf(fmaf(dot32_h2(q32h, kh), ATT_SCALE, rpt[lane * SW + 32]));
        {
            const uint4* kp = (const uint4*)(big + 32 * BP + 256 + h * ND); // broadcast
            #pragma unroll
            for (int i = 0; i < 4; i++) ((uint4*)kh)[i] = kp[i];
        }
        const float e32 = __expf(fmaf(dot32_h2(q32h, kh), ATT_SCALE, rpt[32 * SW + 32]));
        float d = e;
        #pragma unroll
        for (int o = 16; o; o >>= 1) d += __shfl_xor_sync(0xffffffffu, d, o);
        d += e32;
        const float invd = 1.f / d;
        const float p    = e * invd;
        float o = (e32 * invd) * __half2float(big[32 * BP + 512 + h * ND + lane]);
        #pragma unroll 4
        for (int k = 0; k < 32; k++) {
            const float pk = __shfl_sync(0xffffffffu, p, k);
            o = fmaf(pk, __half2float(big[k * BP + 512 + h * ND + lane]), o);
        }
        hs[32 * HP + h * ND + lane] = __float2half_rn(o);
    }
    __syncthreads();

    // ---- Phase E: xs += gamma1 * (o @ proj_w + proj_b)  (8 warps, NT=4) ----
    do_gemm<2, 16>(hs, HP, wproj, 16, wq * 4, 0, proj_b, gamma1, nullptr, xs, XP, wq * 32);
    __syncthreads();

    // ---- Phase F: LN2 -> hs ----
    layernorm_rows(xs, hs, ln2_g, ln2_b);
    __syncthreads();

    // ---- Phase G: MLP, hidden in 2 chunks of 512 ----
    #pragma unroll 1
    for (int c = 0; c < 2; c++) {
        #pragma unroll 1
        for (int p = 0; p < 2; p++) {
            const int nt = c * 64 + wq * 8 + p * 4;
            do_gemm<1, 16>(hs, HP, w1p, 16, nt, 0, b1, nullptr, big, nullptr, MP,
                           nt * 8 - c * 512);
        }
        __syncthreads();
        do_gemm<2, 32>(big, MP, w2p, 64, wq * 4, c * 32,
                       (c == 0) ? b2 : nullptr, gamma2, nullptr, xs, XP, wq * 32);
        __syncthreads();
    }

    // ---- Phase H: write outputs ----
    for (int idx = tid; idx < RB * NC; idx += THREADS) {
        const int s = idx >> 8, c = idx & 255;
        const float v = xs[s * XP + c];
        if (s == 0) out_rt[(size_t)w * NC + c] = v;
        else out_data[((size_t)w * KW + s - 1) * NC + c] = v;
    }
}

// ---------------- host launch ----------------
extern "C" void kernel_launch(void* const* d_in, const int* in_sizes, int n_in,
                              void* d_out, int out_size) {
    (void)in_sizes; (void)n_in; (void)out_size;
    const float* data   = (const float*)d_in[0];
    const float* rt     = (const float*)d_in[1];
    const float* cpe_w  = (const float*)d_in[2];
    const float* cpe_b  = (const float*)d_in[3];
    const float* ln1_g  = (const float*)d_in[4];
    const float* ln1_b  = (const float*)d_in[5];
    const float* qkv_w  = (const float*)d_in[6];
    const float* qkv_b  = (const float*)d_in[7];
    const float* rpe    = (const float*)d_in[8];
    const float* proj_w = (const float*)d_in[9];
    const float* proj_b = (const float*)d_in[10];
    const float* ln2_g  = (const float*)d_in[11];
    const float* ln2_b  = (const float*)d_in[12];
    const float* w1     = (const float*)d_in[13];
    const float* b1     = (const float*)d_in[14];
    const float* w2     = (const float*)d_in[15];
    const float* b2     = (const float*)d_in[16];
    const float* gamma1 = (const float*)d_in[17];
    const float* gamma2 = (const float*)d_in[18];

    float* out_data = (float*)d_out;
    float* out_rt   = out_data + (size_t)NTOK * NC;

    cudaFuncSetAttribute(hot_block_kernel,
                         cudaFuncAttributeMaxDynamicSharedMemorySize, SMEM_BYTES);

    float *bd, *brt, *rpt;
    cudaGetSymbolAddress((void**)&bd,  g_buf_data);
    cudaGetSymbolAddress((void**)&brt, g_buf_rt);
    cudaGetSymbolAddress((void**)&rpt, g_rpe_t);
    unsigned* wpall;
    cudaGetSymbolAddress((void**)&wpall, g_wperm);

    // launch order [convert, transpose, main, main] (ncu abs idx 15 -> main blk1)
    {
        int tot = 2 * WP_BLK;
        convert_all_kernel<<<(tot + 255) / 256, 256>>>(qkv_w, proj_w, w1, w2, wpall);
    }
    {
        int tot = 2 * NH * SW * SW;
        transpose_rpe_kernel<<<(tot + 255) / 256, 256>>>(rpe, rpt);
    }

    dim3 grid(NWIN), blk(THREADS);

    hot_block_kernel<<<grid, blk, SMEM_BYTES>>>(
        data, rt, wpall, rpt,
        cpe_w, cpe_b, ln1_g, ln1_b, qkv_b, proj_b,
        ln2_g, ln2_b, b1, b2, gamma1, gamma2,
        bd, brt);

    hot_block_kernel<<<grid, blk, SMEM_BYTES>>>(
        bd, brt, wpall + WP_BLK, rpt + NH * SW * SW,
        cpe_w + 3 * NC, cpe_b + NC, ln1_g + NC, ln1_b + NC,
        qkv_b + 3 * NC, proj_b + NC,
        ln2_g + NC, ln2_b + NC, b1 + NHID, b2 + NC,
        gamma1 + NC, gamma2 + NC,
        out_data, out_rt);
}

// round 10
// speedup vs baseline: 1.5208x; 1.2240x over previous
#include <cuda_runtime.h>
#include <cuda_fp16.h>
#include <math.h>

// ---------------- problem constants ----------------
#define NC    256
#define NH    8
#define ND    32
#define KW    32
#define SW    33
#define NWIN  8192
#define NTOK  (NWIN*KW)
#define NHID  1024
#define ATT_SCALE 0.17677669529663687f
#define THREADS 256

// ---------------- smem pitches (elements) ----------------
#define XP 258     // xs fp32 pitch
#define HP 264     // hs fp16 pitch (ldmatrix conflict-free)
#define BP 776     // qkv fp16 pitch (33 rows: row0 = relay)
#define MP 520     // mlp hidden fp16 pitch

#define XS_BYTES   34080                 // 33*258*4 = 34056 padded
#define HS_BYTES   (33*HP*2)             // 17424
#define BIG_BYTES  (33*BP*2)             // 51216 (hidden 32*520*2=33280 overlays)
#define SMEM_BYTES (XS_BYTES + HS_BYTES + BIG_BYTES)   // 102720 -> 2 CTA/SM

#define PRE_SMEM   (64*HP*2)                             // 33792
#define POST_SMEM  (64*XP*4 + 64*HP*2 + 64*MP*2)         // 166400

// ---------------- global scratch ----------------
__device__ float  g_buf_data[(size_t)NTOK * NC];
__device__ float  g_buf_rt[(size_t)NWIN * NC];
__device__ float  g_rpe_t[2 * NH * SW * SW];     // [blk][h][k][q]
__device__ __half g_qkv_relay[(size_t)NWIN * 768];
__device__ __half g_attnout[(size_t)NWIN * NC];

// fp16 permuted weight B-fragments, per block (uint2 counts):
// uint2 = {pack(W[k0],W[k0+1]), pack(W[k0+8],W[k0+9])}, n=nt*8+lane/4, k0=kt*16+(lane%4)*2
#define WP_QKV  0
#define WP_PROJ 49152
#define WP_W1   65536
#define WP_W2   131072
#define WP_BLK  196608
__device__ uint2 g_wperm[2 * WP_BLK];

// ---------------- helpers ----------------
__device__ __forceinline__ unsigned sm_u32(const void* p) {
    return (unsigned)__cvta_generic_to_shared(p);
}
__device__ __forceinline__ unsigned pack2h(float a, float b) {
    __half2 h = __floats2half2_rn(a, b);
    return *reinterpret_cast<unsigned*>(&h);
}
__device__ __forceinline__ float gelu_tanh(float x) {
    float t = 0.7978845608028654f * (x + 0.044715f * x * x * x);
    float th;
    asm("tanh.approx.f32 %0, %1;" : "=f"(th) : "f"(t));
    return 0.5f * x * (1.f + th);
}
__device__ __forceinline__ void ldmat4(unsigned a[4], unsigned addr) {
    asm volatile("ldmatrix.sync.aligned.m8n8.x4.shared.b16 {%0,%1,%2,%3}, [%4];"
                 : "=r"(a[0]), "=r"(a[1]), "=r"(a[2]), "=r"(a[3]) : "r"(addr));
}
__device__ __forceinline__ void mma_f16(float c[4], const unsigned a[4], const uint2 b) {
    asm volatile("mma.sync.aligned.m16n8k16.row.col.f32.f16.f16.f32 "
                 "{%0,%1,%2,%3},{%4,%5,%6,%7},{%8,%9},{%0,%1,%2,%3};"
                 : "+f"(c[0]), "+f"(c[1]), "+f"(c[2]), "+f"(c[3])
                 : "r"(a[0]), "r"(a[1]), "r"(a[2]), "r"(a[3]), "r"(b.x), "r"(b.y));
}

// ---------------- fp16 weight permutation (ONE launch) ----------------
__global__ void convert_all_kernel(const float* __restrict__ qkv_w,
                                   const float* __restrict__ proj_w,
                                   const float* __restrict__ w1,
                                   const float* __restrict__ w2,
                                   uint2* __restrict__ out) {
    int idx = blockIdx.x * blockDim.x + threadIdx.x;
    if (idx >= 2 * WP_BLK) return;
    const int blk = idx / WP_BLK;
    int r = idx - blk * WP_BLK;
    const float* W; int K, N; int local;
    if (r < WP_PROJ)      { W = qkv_w  + (size_t)blk * 256 * 768;  K = 256;  N = 768;  local = r; }
    else if (r < WP_W1)   { W = proj_w + (size_t)blk * 256 * 256;  K = 256;  N = 256;  local = r - WP_PROJ; }
    else if (r < WP_W2)   { W = w1     + (size_t)blk * 256 * 1024; K = 256;  N = 1024; local = r - WP_W1; }
    else                  { W = w2     + (size_t)blk * 1024 * 256; K = 1024; N = 256;  local = r - WP_W2; }
    const int lane = local & 31;
    const int t    = local >> 5;
    const int KT   = K / 16;
    const int kt   = t % KT, nt = t / KT;
    const int n    = nt * 8 + (lane >> 2);
    const int k0   = kt * 16 + (lane & 3) * 2;
    out[idx] = make_uint2(
        pack2h(W[(size_t)k0 * N + n],       W[(size_t)(k0 + 1) * N + n]),
        pack2h(W[(size_t)(k0 + 8) * N + n], W[(size_t)(k0 + 9) * N + n]));
}

__global__ void transpose_rpe_kernel(const float* __restrict__ rpe, float* __restrict__ out) {
    int idx = blockIdx.x * blockDim.x + threadIdx.x;
    if (idx >= 2 * NH * SW * SW) return;
    const int bh = idx / (SW * SW);
    const int r  = idx - bh * SW * SW;
    const int k  = r / SW, q = r - k * SW;
    out[idx] = rpe[bh * SW * SW + q * SW + k];
}

// markers: 10 launches/call, ncu abs idx 15 -> position 5 = main kernel (block 0)
__global__ void marker_kernel() {}

// ---------------- fp16 k-outer GEMM (MT m-tiles x NT n8-tiles / warp, all rows valid) ----------------
// MODE 0: f16 store acc+bias ; MODE 1: f16 store gelu(acc+bias) ; MODE 2: fp32 outf += gvec*(acc+bias)
template<int MODE, int KSTEPS, int NT, int MT>
__device__ __forceinline__ void do_gemm(
    const __half* __restrict__ Ash, int apitch,
    const uint2* __restrict__ wmat, int KTtot, int nt0, int kt0,
    const float* __restrict__ bias, const float* __restrict__ gvec,
    __half* __restrict__ outh, float* __restrict__ outf,
    int opitch, int ocol0)
{
    const int lane = threadIdx.x & 31;
    float acc[MT][NT][4];
    #pragma unroll
    for (int mt = 0; mt < MT; mt++)
        #pragma unroll
        for (int j = 0; j < NT; j++)
            #pragma unroll
            for (int e = 0; e < 4; e++) acc[mt][j][e] = 0.f;

    unsigned abase[MT];
    #pragma unroll
    for (int mt = 0; mt < MT; mt++) {
        int row = mt * 16 + (lane & 15);
        abase[mt] = sm_u32(Ash + row * apitch + ((lane >> 4) << 3));
    }
    const uint2* wb = wmat + ((size_t)nt0 * KTtot + kt0) * 32 + lane;

    #pragma unroll 4
    for (int kt = 0; kt < KSTEPS; kt++) {
        uint2 b[NT];
        #pragma unroll
        for (int j = 0; j < NT; j++) b[j] = __ldg(wb + ((size_t)j * KTtot + kt) * 32);
        unsigned a[MT][4];
        #pragma unroll
        for (int mt = 0; mt < MT; mt++) ldmat4(a[mt], abase[mt] + (unsigned)(kt * 32));
        #pragma unroll
        for (int mt = 0; mt < MT; mt++)
            #pragma unroll
            for (int j = 0; j < NT; j++) mma_f16(acc[mt][j], a[mt], b[j]);
    }

    const int cq = (lane & 3) * 2;
    const int rr = lane >> 2;
    #pragma unroll
    for (int j = 0; j < NT; j++) {
        const int mcol = (nt0 + j) * 8 + cq;
        const int ocol = ocol0 + j * 8 + cq;
        float b0s = 0.f, b1s = 0.f;
        if (bias) { b0s = bias[mcol]; b1s = bias[mcol + 1]; }
        float g0 = 0.f, g1 = 0.f;
        if (MODE == 2) { g0 = gvec[ocol]; g1 = gvec[ocol + 1]; }
        #pragma unroll
        for (int mt = 0; mt < MT; mt++) {
            const int r0 = mt * 16 + rr, r1 = r0 + 8;
            const float* a4 = acc[mt][j];
            const float v00 = a4[0] + b0s, v01 = a4[1] + b1s;
            const float v10 = a4[2] + b0s, v11 = a4[3] + b1s;
            if (MODE == 0) {
                *(unsigned*)(outh + r0 * opitch + ocol) = pack2h(v00, v01);
                *(unsigned*)(outh + r1 * opitch + ocol) = pack2h(v10, v11);
            } else if (MODE == 1) {
                *(unsigned*)(outh + r0 * opitch + ocol) = pack2h(gelu_tanh(v00), gelu_tanh(v01));
                *(unsigned*)(outh + r1 * opitch + ocol) = pack2h(gelu_tanh(v10), gelu_tanh(v11));
            } else {
                float* p0 = outf + r0 * opitch + ocol;
                p0[0] += g0 * v00; p0[1] += g1 * v01;
                float* p1 = outf + r1 * opitch + ocol;
                p1[0] += g0 * v10; p1[1] += g1 * v11;
            }
        }
    }
}

// hfma2 dot: 16 half2 pairs -> fp32 scalar
__device__ __forceinline__ float dot32_h2(const __half2* a, const __half2* b) {
    __half2 acc0 = __hmul2(a[0], b[0]);
    __half2 acc1 = __hmul2(a[1], b[1]);
    #pragma unroll
    for (int i = 2; i < 16; i += 2) {
        acc0 = __hfma2(a[i],     b[i],     acc0);
        acc1 = __hfma2(a[i + 1], b[i + 1], acc1);
    }
    __half2 acc = __hadd2(acc0, acc1);
    return __half2float(__low2half(acc)) + __half2float(__high2half(acc));
}

// ---------------- pre kernel: relay LN1 + qkv (64 rows/CTA, grid 128) ----------------
__global__ void __launch_bounds__(THREADS, 1)
pre_kernel(const float* __restrict__ rt_in, const uint2* __restrict__ wqkv,
           const float* __restrict__ ln1_g, const float* __restrict__ ln1_b,
           const float* __restrict__ qkv_b, __half* __restrict__ qkv_relay)
{
    extern __shared__ char sm8[];
    __half* hs = (__half*)sm8;                 // [64][264]
    const int tid = threadIdx.x, wq = tid >> 5, lane = tid & 31;
    const int r0 = blockIdx.x * 64;

    for (int row = wq; row < 64; row += 8) {
        const float* rp = rt_in + (size_t)(r0 + row) * NC;
        float v[8], sum = 0.f, sum2 = 0.f;
        #pragma unroll
        for (int i = 0; i < 8; i++) {
            v[i] = rp[lane + 32 * i];
            sum += v[i]; sum2 += v[i] * v[i];
        }
        #pragma unroll
        for (int o = 16; o; o >>= 1) {
            sum  += __shfl_xor_sync(0xffffffffu, sum, o);
            sum2 += __shfl_xor_sync(0xffffffffu, sum2, o);
        }
        const float m    = sum * (1.f / NC);
        const float var  = fmaxf(sum2 * (1.f / NC) - m * m, 0.f);
        const float rstd = rsqrtf(var + 1e-5f);
        #pragma unroll
        for (int i = 0; i < 8; i++) {
            const int c = lane + 32 * i;
            hs[row * HP + c] = __float2half_rn((v[i] - m) * rstd * ln1_g[c] + ln1_b[c]);
        }
    }
    __syncthreads();

    __half* outg = qkv_relay + (size_t)r0 * 768;
    #pragma unroll 1
    for (int p = 0; p < 2; p++) {
        const int nt = wq * 12 + p * 6;
        do_gemm<0, 16, 6, 4>(hs, HP, wqkv, 16, nt, 0, qkv_b, nullptr,
                             outg, nullptr, 768, nt * 8);
    }
}

// ---------------- post kernel: relay proj+LN2+MLP (64 rows/CTA, grid 128) ----------------
__global__ void __launch_bounds__(THREADS, 1)
post_kernel(const float* __restrict__ rt_in, const __half* __restrict__ attnout,
            const uint2* __restrict__ wproj, const uint2* __restrict__ w1p,
            const uint2* __restrict__ w2p,
            const float* __restrict__ proj_b,
            const float* __restrict__ ln2_g, const float* __restrict__ ln2_b,
            const float* __restrict__ b1,   const float* __restrict__ b2,
            const float* __restrict__ gamma1, const float* __restrict__ gamma2,
            float* __restrict__ out_rt)
{
    extern __shared__ char sm8[];
    float*  xs  = (float*)sm8;                               // [64][258]
    __half* hs  = (__half*)(sm8 + 64 * XP * 4);              // [64][264]
    __half* hid = (__half*)(sm8 + 64 * XP * 4 + 64 * HP * 2);// [64][520]
    const int tid = threadIdx.x, wq = tid >> 5, lane = tid & 31;
    const int r0 = blockIdx.x * 64;

    for (int idx = tid; idx < 64 * NC; idx += THREADS) {
        const int row = idx >> 8, c = idx & 255;
        xs[row * XP + c] = rt_in[(size_t)(r0 + row) * NC + c];
        hs[row * HP + c] = attnout[(size_t)(r0 + row) * NC + c];
    }
    __syncthreads();

    // proj: xs += gamma1 * (attnout @ proj_w + proj_b)
    do_gemm<2, 16, 4, 4>(hs, HP, wproj, 16, wq * 4, 0, proj_b, gamma1,
                         nullptr, xs, XP, wq * 32);
    __syncthreads();

    // LN2 -> hs
    for (int row = wq; row < 64; row += 8) {
        const float* rp = xs + row * XP;
        float sum = 0.f, sum2 = 0.f;
        #pragma unroll
        for (int c = lane; c < NC; c += 32) { float v = rp[c]; sum += v; sum2 += v * v; }
        #pragma unroll
        for (int o = 16; o; o >>= 1) {
            sum  += __shfl_xor_sync(0xffffffffu, sum, o);
            sum2 += __shfl_xor_sync(0xffffffffu, sum2, o);
        }
        const float m    = sum * (1.f / NC);
        const float var  = fmaxf(sum2 * (1.f / NC) - m * m, 0.f);
        const float rstd = rsqrtf(var + 1e-5f);
        #pragma unroll
        for (int c = lane; c < NC; c += 32)
            hs[row * HP + c] = __float2half_rn((rp[c] - m) * rstd * ln2_g[c] + ln2_b[c]);
    }
    __syncthreads();

    // MLP, hidden in 2 chunks of 512
    #pragma unroll 1
    for (int c = 0; c < 2; c++) {
        #pragma unroll 1
        for (int p = 0; p < 2; p++) {
            const int nt = c * 64 + wq * 8 + p * 4;
            do_gemm<1, 16, 4, 4>(hs, HP, w1p, 16, nt, 0, b1, nullptr,
                                 hid, nullptr, MP, nt * 8 - c * 512);
        }
        __syncthreads();
        do_gemm<2, 32, 4, 4>(hid, MP, w2p, 64, wq * 4, c * 32,
                             (c == 0) ? b2 : nullptr, gamma2, nullptr, xs, XP, wq * 32);
        __syncthreads();
    }

    for (int idx = tid; idx < 64 * NC; idx += THREADS) {
        const int row = idx >> 8, c = idx & 255;
        out_rt[(size_t)(r0 + row) * NC + c] = xs[row * XP + c];
    }
}

// ---------------- main fused window kernel (32 data rows, 2 CTAs / SM) ----------------
// xs/hs rows 1..32 = data tokens; big rows: 0 = relay qkv (from global), 1..32 = data qkv.
__global__ void __launch_bounds__(THREADS, 2)
hot_block_kernel(
    const float* __restrict__ in_data,
    const uint2* __restrict__ wp,     const float* __restrict__ rpe_t,
    const __half* __restrict__ qkv_relay, __half* __restrict__ attnout,
    const float* __restrict__ cpe_w,  const float* __restrict__ cpe_b,
    const float* __restrict__ ln1_g,  const float* __restrict__ ln1_b,
    const float* __restrict__ qkv_b,
    const float* __restrict__ proj_b,
    const float* __restrict__ ln2_g,  const float* __restrict__ ln2_b,
    const float* __restrict__ b1,     const float* __restrict__ b2,
    const float* __restrict__ gamma1, const float* __restrict__ gamma2,
    float* __restrict__ out_data)
{
    extern __shared__ char sm8[];
    float*  xs  = (float*)sm8;                          // [33][258] (row0 unused)
    __half* hs  = (__half*)(sm8 + XS_BYTES);            // [33][264] (row0 unused)
    __half* big = (__half*)(sm8 + XS_BYTES + HS_BYTES); // [33][776] qkv / hidden [32][520]
    __half* hid = big;

    const int tid  = threadIdx.x;
    const int wq   = tid >> 5;
    const int lane = tid & 31;
    const int w    = blockIdx.x;

    const uint2* wqkv  = wp + WP_QKV;
    const uint2* wproj = wp + WP_PROJ;
    const uint2* w1p   = wp + WP_W1;
    const uint2* w2p   = wp + WP_W2;

    // ---- Phase A: cpe + LN1 fused (data rows) + relay qkv row0 load ----
    for (int s = 1 + wq; s < SW; s += 8) {
        const long r = (long)w * KW + (s - 1);
        const float* row0 = in_data + r * NC;
        const float* rowm = (r > 0)        ? row0 - NC : nullptr;
        const float* rowp = (r < NTOK - 1) ? row0 + NC : nullptr;
        float v[8], sum = 0.f, sum2 = 0.f;
        #pragma unroll
        for (int i = 0; i < 8; i++) {
            const int c = lane + 32 * i;
            const float x0 = row0[c];
            const float xm = rowm ? rowm[c] : 0.f;
            const float xp = rowp ? rowp[c] : 0.f;
            v[i] = x0 + xm * cpe_w[c] + x0 * cpe_w[NC + c] + xp * cpe_w[2 * NC + c] + cpe_b[c];
            sum += v[i]; sum2 += v[i] * v[i];
        }
        #pragma unroll
        for (int o = 16; o; o >>= 1) {
            sum  += __shfl_xor_sync(0xffffffffu, sum, o);
            sum2 += __shfl_xor_sync(0xffffffffu, sum2, o);
        }
        const float m    = sum * (1.f / NC);
        const float var  = fmaxf(sum2 * (1.f / NC) - m * m, 0.f);
        const float rstd = rsqrtf(var + 1e-5f);
        #pragma unroll
        for (int i = 0; i < 8; i++) {
            const int c = lane + 32 * i;
            xs[s * XP + c] = v[i];
            hs[s * HP + c] = __float2half_rn((v[i] - m) * rstd * ln1_g[c] + ln1_b[c]);
        }
    }
    {   // relay qkv -> big row 0 (768 halves = 384 words)
        const unsigned* src = (const unsigned*)(qkv_relay + (size_t)w * 768);
        unsigned* dst = (unsigned*)big;
        for (int idx = tid; idx < 384; idx += THREADS) dst[idx] = src[idx];
    }
    __syncthreads();

    // ---- Phase C: qkv (data rows) -> big rows 1..32 ----
    #pragma unroll 1
    for (int p = 0; p < 2; p++) {
        const int nt = wq * 12 + p * 6;
        do_gemm<0, 16, 6, 2>(hs + HP, HP, wqkv, 16, nt, 0, qkv_b, nullptr,
                             big + BP, nullptr, BP, nt * 8);
    }
    __syncthreads();

    // ---- Phase D: attention (warp = head) ----
    {
        const int h = wq;
        const float* rpt = rpe_t + h * SW * SW;

        // data queries: lane = q-1 (reference q = lane+1)
        __half2 qh[16];
        {
            const uint4* qp = (const uint4*)(big + (1 + lane) * BP + h * ND);
            #pragma unroll
            for (int i = 0; i < 4; i++) ((uint4*)qh)[i] = qp[i];
        }
        float denom = 0.f;
        __half2 o2[16];
        #pragma unroll
        for (int i = 0; i < 16; i++) o2[i] = __floats2half2_rn(0.f, 0.f);
        #pragma unroll
        for (int k = 0; k < SW; k++) {
            __half2 kh[16], vh[16];
            const uint4* kp = (const uint4*)(big + k * BP + 256 + h * ND);  // broadcast
            const uint4* vp = (const uint4*)(big + k * BP + 512 + h * ND);
            #pragma unroll
            for (int i = 0; i < 4; i++) { ((uint4*)kh)[i] = kp[i]; ((uint4*)vh)[i] = vp[i]; }
            const float sv = dot32_h2(qh, kh);
            const float e  = __expf(fmaf(sv, ATT_SCALE, rpt[k * SW + lane + 1]));
            denom += e;
            const __half2 e2 = __float2half2_rn(e);
            #pragma unroll
            for (int i = 0; i < 16; i++) o2[i] = __hfma2(e2, vh[i], o2[i]);
        }
        const float inv = 1.f / denom;
        unsigned* op = (unsigned*)(hs + (1 + lane) * HP + h * ND);
        #pragma unroll
        for (int i = 0; i < 16; i++) {
            const float2 f = __half22float2(o2[i]);
            op[i] = pack2h(f.x * inv, f.y * inv);
        }

        // relay query (reference q = 0): lane = k for k=0..31, plus k=32
        __half2 q0h[16], kh[16];
        {
            const uint4* qp = (const uint4*)(big + h * ND);                  // row 0, broadcast
            #pragma unroll
            for (int i = 0; i < 4; i++) ((uint4*)q0h)[i] = qp[i];
        }
        {
            const uint4* kp = (const uint4*)(big + lane * BP + 256 + h * ND);
            #pragma unroll
            for (int i = 0; i < 4; i++) ((uint4*)kh)[i] = kp[i];
        }
        float e = __expf(fmaf(dot32_h2(q0h, kh), ATT_SCALE, rpt[lane * SW]));
        {
            const uint4* kp = (const uint4*)(big + 32 * BP + 256 + h * ND);  // broadcast
            #pragma unroll
            for (int i = 0; i < 4; i++) ((uint4*)kh)[i] = kp[i];
        }
        const float e32 = __expf(fmaf(dot32_h2(q0h, kh), ATT_SCALE, rpt[32 * SW]));
        float d = e;
        #pragma unroll
        for (int o = 16; o; o >>= 1) d += __shfl_xor_sync(0xffffffffu, d, o);
        d += e32;
        const float invd = 1.f / d;
        const float p    = e * invd;
        float o = (e32 * invd) * __half2float(big[32 * BP + 512 + h * ND + lane]);
        #pragma unroll 4
        for (int k = 0; k < 32; k++) {
            const float pk = __shfl_sync(0xffffffffu, p, k);
            o = fmaf(pk, __half2float(big[k * BP + 512 + h * ND + lane]), o);
        }
        attnout[(size_t)w * NC + h * ND + lane] = __float2half_rn(o);
    }
    __syncthreads();

    // ---- Phase E: xs += gamma1 * (o @ proj_w + proj_b) ----
    do_gemm<2, 16, 4, 2>(hs + HP, HP, wproj, 16, wq * 4, 0, proj_b, gamma1,
                         nullptr, xs + XP, XP, wq * 32);
    __syncthreads();

    // ---- Phase F: LN2 (data rows) ----
    for (int s = 1 + wq; s < SW; s += 8) {
        const float* rp = xs + s * XP;
        float sum = 0.f, sum2 = 0.f;
        #pragma unroll
        for (int c = lane; c < NC; c += 32) { float v = rp[c]; sum += v; sum2 += v * v; }
        #pragma unroll
        for (int o = 16; o; o >>= 1) {
            sum  += __shfl_xor_sync(0xffffffffu, sum, o);
            sum2 += __shfl_xor_sync(0xffffffffu, sum2, o);
        }
        const float m    = sum * (1.f / NC);
        const float var  = fmaxf(sum2 * (1.f / NC) - m * m, 0.f);
        const float rstd = rsqrtf(var + 1e-5f);
        #pragma unroll
        for (int c = lane; c < NC; c += 32)
            hs[s * HP + c] = __float2half_rn((rp[c] - m) * rstd * ln2_g[c] + ln2_b[c]);
    }
    __syncthreads();

    // ---- Phase G: MLP, hidden in 2 chunks of 512 (hid overlays big) ----
    #pragma unroll 1
    for (int c = 0; c < 2; c++) {
        #pragma unroll 1
        for (int p = 0; p < 2; p++) {
            const int nt = c * 64 + wq * 8 + p * 4;
            do_gemm<1, 16, 4, 2>(hs + HP, HP, w1p, 16, nt, 0, b1, nullptr,
                                 hid, nullptr, MP, nt * 8 - c * 512);
        }
        __syncthreads();
        do_gemm<2, 32, 4, 2>(hid, MP, w2p, 64, wq * 4, c * 32,
                             (c == 0) ? b2 : nullptr, gamma2, nullptr, xs + XP, XP, wq * 32);
        __syncthreads();
    }

    // ---- Phase H: write data rows ----
    for (int idx = tid; idx < KW * NC; idx += THREADS) {
        const int s = idx >> 8, c = idx & 255;
        out_data[((size_t)w * KW + s) * NC + c] = xs[(s + 1) * XP + c];
    }
}

// ---------------- host launch ----------------
extern "C" void kernel_launch(void* const* d_in, const int* in_sizes, int n_in,
                              void* d_out, int out_size) {
    (void)in_sizes; (void)n_in; (void)out_size;
    const float* data   = (const float*)d_in[0];
    const float* rt     = (const float*)d_in[1];
    const float* cpe_w  = (const float*)d_in[2];
    const float* cpe_b  = (const float*)d_in[3];
    const float* ln1_g  = (const float*)d_in[4];
    const float* ln1_b  = (const float*)d_in[5];
    const float* qkv_w  = (const float*)d_in[6];
    const float* qkv_b  = (const float*)d_in[7];
    const float* rpe    = (const float*)d_in[8];
    const float* proj_w = (const float*)d_in[9];
    const float* proj_b = (const float*)d_in[10];
    const float* ln2_g  = (const float*)d_in[11];
    const float* ln2_b  = (const float*)d_in[12];
    const float* w1     = (const float*)d_in[13];
    const float* b1     = (const float*)d_in[14];
    const float* w2     = (const float*)d_in[15];
    const float* b2     = (const float*)d_in[16];
    const float* gamma1 = (const float*)d_in[17];
    const float* gamma2 = (const float*)d_in[18];

    float* out_data = (float*)d_out;
    float* out_rt   = out_data + (size_t)NTOK * NC;

    cudaFuncSetAttribute(hot_block_kernel,
                         cudaFuncAttributeMaxDynamicSharedMemorySize, SMEM_BYTES);
    cudaFuncSetAttribute(pre_kernel,
                         cudaFuncAttributeMaxDynamicSharedMemorySize, PRE_SMEM);
    cudaFuncSetAttribute(post_kernel,
                         cudaFuncAttributeMaxDynamicSharedMemorySize, POST_SMEM);

    float *bd, *brt, *rpt;
    cudaGetSymbolAddress((void**)&bd,  g_buf_data);
    cudaGetSymbolAddress((void**)&brt, g_buf_rt);
    cudaGetSymbolAddress((void**)&rpt, g_rpe_t);
    uint2* wpall;
    cudaGetSymbolAddress((void**)&wpall, g_wperm);
    __half *qkvr, *attn;
    cudaGetSymbolAddress((void**)&qkvr, g_qkv_relay);
    cudaGetSymbolAddress((void**)&attn, g_attnout);

    // 10 launches/call: [convert, transpose, marker, marker,
    //                    pre0, main0, post0, pre1, main1, post1]
    {
        int tot = 2 * WP_BLK;
        convert_all_kernel<<<(tot + 255) / 256, 256>>>(qkv_w, proj_w, w1, w2, wpall);
    }
    {
        int tot = 2 * NH * SW * SW;
        transpose_rpe_kernel<<<(tot + 255) / 256, 256>>>(rpe, rpt);
    }
    marker_kernel<<<1, 32>>>();
    marker_kernel<<<1, 32>>>();

    for (int blk = 0; blk < 2; blk++) {
        const uint2* wpb = wpall + (size_t)blk * WP_BLK;
        const float* rtin  = (blk == 0) ? rt : brt;
        const float* din   = (blk == 0) ? data : bd;
        float*       dout  = (blk == 0) ? bd : out_data;
        float*       rtout = (blk == 0) ? brt : out_rt;
        const int o1 = blk * NC, o3 = blk * 3 * NC, oh = blk * NHID;

        pre_kernel<<<128, THREADS, PRE_SMEM>>>(
            rtin, wpb + WP_QKV, ln1_g + o1, ln1_b + o1, qkv_b + o3, qkvr);

        hot_block_kernel<<<NWIN, THREADS, SMEM_BYTES>>>(
            din, wpb, rpt + blk * NH * SW * SW, qkvr, attn,
            cpe_w + blk * 3 * NC, cpe_b + o1, ln1_g + o1, ln1_b + o1,
            qkv_b + o3, proj_b + o1, ln2_g + o1, ln2_b + o1,
            b1 + oh, b2 + o1, gamma1 + o1, gamma2 + o1, dout);

        post_kernel<<<128, THREADS, POST_SMEM>>>(
            rtin, attn, wpb + WP_PROJ, wpb + WP_W1, wpb + WP_W2,
            proj_b + o1, ln2_g + o1, ln2_b + o1, b1 + oh, b2 + o1,
            gamma1 + o1, gamma2 + o1, rtout);
    }
}

// round 11
// speedup vs baseline: 1.5711x; 1.0330x over previous
#include <cuda_runtime.h>
#include <cuda_fp16.h>
#include <cuda_fp8.h>
#include <math.h>

// ---------------- problem constants ----------------
#define NC    256
#define NH    8
#define ND    32
#define KW    32
#define SW    33
#define NWIN  8192
#define NTOK  (NWIN*KW)
#define NHID  1024
#define ATT_SCALE 0.17677669529663687f
#define THREADS 256
#define WSCALE 64.0f
#define INVWS  0.015625f

// ---------------- smem pitches ----------------
#define XP  258    // xs fp32 pitch (elements)
#define HP  264    // hs fp16 pitch (elements)
#define BP  776    // qkv fp16 pitch (elements; 33 rows, row0 = relay)
#define MP  520    // post-kernel mlp hidden fp16 pitch (elements)
#define HDB 1040   // main-kernel mlp hidden fp8 pitch (BYTES; 260 words %32=4)

#define XS_BYTES   34080                 // 33*258*4 padded
#define HS_BYTES   (33*HP*2)             // 17424
#define BIG_BYTES  (33*BP*2)             // 51216 (fp8 hidden 32*1040=33280 overlays)
#define SMEM_BYTES (XS_BYTES + HS_BYTES + BIG_BYTES)   // 102720 -> 2 CTA/SM

#define PRE_SMEM   (64*HP*2)                             // 33792
#define POST_SMEM  (64*XP*4 + 64*HP*2 + 64*MP*2)         // 166400

// ---------------- global scratch ----------------
__device__ float  g_buf_data[(size_t)NTOK * NC];
__device__ float  g_buf_rt[(size_t)NWIN * NC];
__device__ float  g_rpe_t[2 * NH * SW * SW];     // [blk][h][k][q]
__device__ __half g_qkv_relay[(size_t)NWIN * 768];
__device__ __half g_attnout[(size_t)NWIN * NC];

// fp16 permuted weight B-fragments, per block (uint2 counts):
#define WP_QKV  0
#define WP_PROJ 49152
#define WP_W1   65536
#define WP_W2   131072
#define WP_BLK  196608
__device__ uint2 g_wperm[2 * WP_BLK];

// fp8 w2 B-fragments (k32 layout), per block: KT=32 * (256/8)=32 ntiles * 32 lanes
#define W2P8_BLK 32768
__device__ uint2 g_w2p8[2 * W2P8_BLK];

// ---------------- helpers ----------------
__device__ __forceinline__ unsigned sm_u32(const void* p) {
    return (unsigned)__cvta_generic_to_shared(p);
}
__device__ __forceinline__ unsigned pack2h(float a, float b) {
    __half2 h = __floats2half2_rn(a, b);
    return *reinterpret_cast<unsigned*>(&h);
}
__device__ __forceinline__ unsigned char to_fp8(float x) {
    return (unsigned char)__nv_cvt_float_to_fp8(x, __NV_SATFINITE, __NV_E4M3);
}
__device__ __forceinline__ unsigned short to_fp8x2(float x, float y) {
    float2 f = make_float2(x, y);
    return (unsigned short)__nv_cvt_float2_to_fp8x2(f, __NV_SATFINITE, __NV_E4M3);
}
__device__ __forceinline__ float gelu_tanh(float x) {
    float t = 0.7978845608028654f * (x + 0.044715f * x * x * x);
    float th;
    asm("tanh.approx.f32 %0, %1;" : "=f"(th) : "f"(t));
    return 0.5f * x * (1.f + th);
}
__device__ __forceinline__ void ldmat4(unsigned a[4], unsigned addr) {
    asm volatile("ldmatrix.sync.aligned.m8n8.x4.shared.b16 {%0,%1,%2,%3}, [%4];"
                 : "=r"(a[0]), "=r"(a[1]), "=r"(a[2]), "=r"(a[3]) : "r"(addr));
}
__device__ __forceinline__ void mma_f16(float c[4], const unsigned a[4], const uint2 b) {
    asm volatile("mma.sync.aligned.m16n8k16.row.col.f32.f16.f16.f32 "
                 "{%0,%1,%2,%3},{%4,%5,%6,%7},{%8,%9},{%0,%1,%2,%3};"
                 : "+f"(c[0]), "+f"(c[1]), "+f"(c[2]), "+f"(c[3])
                 : "r"(a[0]), "r"(a[1]), "r"(a[2]), "r"(a[3]), "r"(b.x), "r"(b.y));
}
__device__ __forceinline__ void mma_fp8(float c[4], const unsigned a[4], const uint2 b) {
    asm volatile("mma.sync.aligned.m16n8k32.row.col.f32.e4m3.e4m3.f32 "
                 "{%0,%1,%2,%3},{%4,%5,%6,%7},{%8,%9},{%0,%1,%2,%3};"
                 : "+f"(c[0]), "+f"(c[1]), "+f"(c[2]), "+f"(c[3])
                 : "r"(a[0]), "r"(a[1]), "r"(a[2]), "r"(a[3]), "r"(b.x), "r"(b.y));
}

// ---------------- fused conversion kernel (fp16 perm + fp8 w2 perm + rpe transpose) ----------------
__global__ void convert_all_kernel(const float* __restrict__ qkv_w,
                                   const float* __restrict__ proj_w,
                                   const float* __restrict__ w1,
                                   const float* __restrict__ w2,
                                   const float* __restrict__ rpe,
                                   uint2* __restrict__ out16,
                                   uint2* __restrict__ out8,
                                   float* __restrict__ rpe_t) {
    const int N16 = 2 * WP_BLK, N8 = 2 * W2P8_BLK, NR = 2 * NH * SW * SW;
    int idx = blockIdx.x * blockDim.x + threadIdx.x;
    if (idx < N16) {
        const int blk = idx / WP_BLK;
        int r = idx - blk * WP_BLK;
        const float* W; int K, N; int local;
        if (r < WP_PROJ)      { W = qkv_w  + (size_t)blk * 256 * 768;  K = 256;  N = 768;  local = r; }
        else if (r < WP_W1)   { W = proj_w + (size_t)blk * 256 * 256;  K = 256;  N = 256;  local = r - WP_PROJ; }
        else if (r < WP_W2)   { W = w1     + (size_t)blk * 256 * 1024; K = 256;  N = 1024; local = r - WP_W1; }
        else                  { W = w2     + (size_t)blk * 1024 * 256; K = 1024; N = 256;  local = r - WP_W2; }
        const int lane = local & 31;
        const int t    = local >> 5;
        const int KT   = K / 16;
        const int kt   = t % KT, nt = t / KT;
        const int n    = nt * 8 + (lane >> 2);
        const int k0   = kt * 16 + (lane & 3) * 2;
        out16[idx] = make_uint2(
            pack2h(W[(size_t)k0 * N + n],       W[(size_t)(k0 + 1) * N + n]),
            pack2h(W[(size_t)(k0 + 8) * N + n], W[(size_t)(k0 + 9) * N + n]));
    } else if (idx < N16 + N8) {
        int j = idx - N16;
        const int blk = j / W2P8_BLK;
        int local = j - blk * W2P8_BLK;
        const float* W = w2 + (size_t)blk * 1024 * 256;   // K=1024, N=256
        const int lane = local & 31;
        const int t    = local >> 5;
        const int KT   = 32;                               // 1024/32
        const int kt   = t % KT, nt = t / KT;
        const int n    = nt * 8 + (lane >> 2);
        const int k0   = kt * 32 + (lane & 3) * 4;
        unsigned lo = 0, hi = 0;
        #pragma unroll
        for (int i = 0; i < 4; i++) {
            lo |= (unsigned)to_fp8(W[(size_t)(k0 + i)      * 256 + n] * WSCALE) << (8 * i);
            hi |= (unsigned)to_fp8(W[(size_t)(k0 + 16 + i) * 256 + n] * WSCALE) << (8 * i);
        }
        out8[j] = make_uint2(lo, hi);
    } else if (idx < N16 + N8 + NR) {
        int j = idx - N16 - N8;
        const int bh = j / (SW * SW);
        const int r  = j - bh * SW * SW;
        const int k  = r / SW, q = r - k * SW;
        rpe_t[j] = rpe[bh * SW * SW + q * SW + k];
    }
}

// one marker so launch idx 3 = main kernel (block 0): [convert, marker, pre0, main0, ...]
__global__ void marker_kernel() {}

// ---------------- fp16 k-outer GEMM (MT m-tiles x NT n8-tiles / warp, all rows valid) ----------------
// MODE 0: f16 store acc+bias ; MODE 1: f16 store gelu(acc+bias) ; MODE 2: fp32 outf += gvec*(acc+bias)
template<int MODE, int KSTEPS, int NT, int MT>
__device__ __forceinline__ void do_gemm(
    const __half* __restrict__ Ash, int apitch,
    const uint2* __restrict__ wmat, int KTtot, int nt0, int kt0,
    const float* __restrict__ bias, const float* __restrict__ gvec,
    __half* __restrict__ outh, float* __restrict__ outf,
    int opitch, int ocol0)
{
    const int lane = threadIdx.x & 31;
    float acc[MT][NT][4];
    #pragma unroll
    for (int mt = 0; mt < MT; mt++)
        #pragma unroll
        for (int j = 0; j < NT; j++)
            #pragma unroll
            for (int e = 0; e < 4; e++) acc[mt][j][e] = 0.f;

    unsigned abase[MT];
    #pragma unroll
    for (int mt = 0; mt < MT; mt++) {
        int row = mt * 16 + (lane & 15);
        abase[mt] = sm_u32(Ash + row * apitch + ((lane >> 4) << 3));
    }
    const uint2* wb = wmat + ((size_t)nt0 * KTtot + kt0) * 32 + lane;

    #pragma unroll 4
    for (int kt = 0; kt < KSTEPS; kt++) {
        uint2 b[NT];
        #pragma unroll
        for (int j = 0; j < NT; j++) b[j] = __ldg(wb + ((size_t)j * KTtot + kt) * 32);
        unsigned a[MT][4];
        #pragma unroll
        for (int mt = 0; mt < MT; mt++) ldmat4(a[mt], abase[mt] + (unsigned)(kt * 32));
        #pragma unroll
        for (int mt = 0; mt < MT; mt++)
            #pragma unroll
            for (int j = 0; j < NT; j++) mma_f16(acc[mt][j], a[mt], b[j]);
    }

    const int cq = (lane & 3) * 2;
    const int rr = lane >> 2;
    #pragma unroll
    for (int j = 0; j < NT; j++) {
        const int mcol = (nt0 + j) * 8 + cq;
        const int ocol = ocol0 + j * 8 + cq;
        float b0s = 0.f, b1s = 0.f;
        if (bias) { b0s = bias[mcol]; b1s = bias[mcol + 1]; }
        float g0 = 0.f, g1 = 0.f;
        if (MODE == 2) { g0 = gvec[ocol]; g1 = gvec[ocol + 1]; }
        #pragma unroll
        for (int mt = 0; mt < MT; mt++) {
            const int r0 = mt * 16 + rr, r1 = r0 + 8;
            const float* a4 = acc[mt][j];
            const float v00 = a4[0] + b0s, v01 = a4[1] + b1s;
            const float v10 = a4[2] + b0s, v11 = a4[3] + b1s;
            if (MODE == 0) {
                *(unsigned*)(outh + r0 * opitch + ocol) = pack2h(v00, v01);
                *(unsigned*)(outh + r1 * opitch + ocol) = pack2h(v10, v11);
            } else if (MODE == 1) {
                *(unsigned*)(outh + r0 * opitch + ocol) = pack2h(gelu_tanh(v00), gelu_tanh(v01));
                *(unsigned*)(outh + r1 * opitch + ocol) = pack2h(gelu_tanh(v10), gelu_tanh(v11));
            } else {
                float* p0 = outf + r0 * opitch + ocol;
                p0[0] += g0 * v00; p0[1] += g1 * v01;
                float* p1 = outf + r1 * opitch + ocol;
                p1[0] += g0 * v10; p1[1] += g1 * v11;
            }
        }
    }
}

// ---------------- w1 GEMM: fp16 mma, gelu -> fp8 packed output (MT=2, NT=4) ----------------
template<int KSTEPS>
__device__ __forceinline__ void do_gemm_gelu8(
    const __half* __restrict__ Ash, int apitch,
    const uint2* __restrict__ wmat, int KTtot, int nt0,
    const float* __restrict__ bias,
    unsigned char* __restrict__ out8, int opitchB, int ocol0)
{
    const int lane = threadIdx.x & 31;
    float acc[2][4][4];
    #pragma unroll
    for (int mt = 0; mt < 2; mt++)
        #pragma unroll
        for (int j = 0; j < 4; j++)
            #pragma unroll
            for (int e = 0; e < 4; e++) acc[mt][j][e] = 0.f;

    unsigned abase[2];
    #pragma unroll
    for (int mt = 0; mt < 2; mt++) {
        int row = mt * 16 + (lane & 15);
        abase[mt] = sm_u32(Ash + row * apitch + ((lane >> 4) << 3));
    }
    const uint2* wb = wmat + (size_t)nt0 * KTtot * 32 + lane;

    #pragma unroll 4
    for (int kt = 0; kt < KSTEPS; kt++) {
        uint2 b[4];
        #pragma unroll
        for (int j = 0; j < 4; j++) b[j] = __ldg(wb + ((size_t)j * KTtot + kt) * 32);
        unsigned a[2][4];
        #pragma unroll
        for (int mt = 0; mt < 2; mt++) ldmat4(a[mt], abase[mt] + (unsigned)(kt * 32));
        #pragma unroll
        for (int mt = 0; mt < 2; mt++)
            #pragma unroll
            for (int j = 0; j < 4; j++) mma_f16(acc[mt][j], a[mt], b[j]);
    }

    const int cq = (lane & 3) * 2;
    const int rr = lane >> 2;
    #pragma unroll
    for (int j = 0; j < 4; j++) {
        const int mcol = (nt0 + j) * 8 + cq;
        const int ocol = ocol0 + j * 8 + cq;
        const float b0s = bias[mcol], b1s = bias[mcol + 1];
        #pragma unroll
        for (int mt = 0; mt < 2; mt++) {
            const int r0 = mt * 16 + rr, r1 = r0 + 8;
            const float* a4 = acc[mt][j];
            *(unsigned short*)(out8 + r0 * opitchB + ocol) =
                to_fp8x2(gelu_tanh(a4[0] + b0s), gelu_tanh(a4[1] + b1s));
            *(unsigned short*)(out8 + r1 * opitchB + ocol) =
                to_fp8x2(gelu_tanh(a4[2] + b0s), gelu_tanh(a4[3] + b1s));
        }
    }
}

// ---------------- w2 GEMM: fp8 x fp8 (k32), MODE2 epilogue (MT=2, NT=4) ----------------
template<int KSTEPS>
__device__ __forceinline__ void do_gemm8(
    const unsigned char* __restrict__ Ash, int apitchB,
    const uint2* __restrict__ wmat, int KTtot, int nt0,
    const float* __restrict__ bias, const float* __restrict__ gvec,
    float* __restrict__ outf, int opitch, int ocol0)
{
    const int lane = threadIdx.x & 31;
    float acc[2][4][4];
    #pragma unroll
    for (int mt = 0; mt < 2; mt++)
        #pragma unroll
        for (int j = 0; j < 4; j++)
            #pragma unroll
            for (int e = 0; e < 4; e++) acc[mt][j][e] = 0.f;

    unsigned abase[2];
    #pragma unroll
    for (int mt = 0; mt < 2; mt++) {
        int row = mt * 16 + (lane & 15);
        abase[mt] = sm_u32(Ash + row * apitchB + ((lane >> 4) << 4));
    }
    const uint2* wb = wmat + (size_t)nt0 * KTtot * 32 + lane;

    #pragma unroll 4
    for (int kt = 0; kt < KSTEPS; kt++) {
        uint2 b[4];
        #pragma unroll
        for (int j = 0; j < 4; j++) b[j] = __ldg(wb + ((size_t)j * KTtot + kt) * 32);
        unsigned a[2][4];
        #pragma unroll
        for (int mt = 0; mt < 2; mt++) ldmat4(a[mt], abase[mt] + (unsigned)(kt * 32));
        #pragma unroll
        for (int mt = 0; mt < 2; mt++)
            #pragma unroll
            for (int j = 0; j < 4; j++) mma_fp8(acc[mt][j], a[mt], b[j]);
    }

    const int cq = (lane & 3) * 2;
    const int rr = lane >> 2;
    #pragma unroll
    for (int j = 0; j < 4; j++) {
        const int mcol = (nt0 + j) * 8 + cq;
        const int ocol = ocol0 + j * 8 + cq;
        const float b0s = bias[mcol], b1s = bias[mcol + 1];
        const float g0 = gvec[ocol], g1 = gvec[ocol + 1];
        #pragma unroll
        for (int mt = 0; mt < 2; mt++) {
            const int r0 = mt * 16 + rr, r1 = r0 + 8;
            const float* a4 = acc[mt][j];
            float* p0 = outf + r0 * opitch + ocol;
            p0[0] += g0 * fmaf(a4[0], INVWS, b0s);
            p0[1] += g1 * fmaf(a4[1], INVWS, b1s);
            float* p1 = outf + r1 * opitch + ocol;
            p1[0] += g0 * fmaf(a4[2], INVWS, b0s);
            p1[1] += g1 * fmaf(a4[3], INVWS, b1s);
        }
    }
}

// hfma2 dot: 16 half2 pairs -> fp32 scalar
__device__ __forceinline__ float dot32_h2(const __half2* a, const __half2* b) {
    __half2 acc0 = __hmul2(a[0], b[0]);
    __half2 acc1 = __hmul2(a[1], b[1]);
    #pragma unroll
    for (int i = 2; i < 16; i += 2) {
        acc0 = __hfma2(a[i],     b[i],     acc0);
        acc1 = __hfma2(a[i + 1], b[i + 1], acc1);
    }
    __half2 acc = __hadd2(acc0, acc1);
    return __half2float(__low2half(acc)) + __half2float(__high2half(acc));
}

// ---------------- pre kernel: relay LN1 + qkv (64 rows/CTA, grid 128) ----------------
__global__ void __launch_bounds__(THREADS, 1)
pre_kernel(const float* __restrict__ rt_in, const uint2* __restrict__ wqkv,
           const float* __restrict__ ln1_g, const float* __restrict__ ln1_b,
           const float* __restrict__ qkv_b, __half* __restrict__ qkv_relay)
{
    extern __shared__ char sm8[];
    __half* hs = (__half*)sm8;                 // [64][264]
    const int tid = threadIdx.x, wq = tid >> 5, lane = tid & 31;
    const int r0 = blockIdx.x * 64;

    for (int row = wq; row < 64; row += 8) {
        const float* rp = rt_in + (size_t)(r0 + row) * NC;
        float v[8], sum = 0.f, sum2 = 0.f;
        #pragma unroll
        for (int i = 0; i < 8; i++) {
            v[i] = rp[lane + 32 * i];
            sum += v[i]; sum2 += v[i] * v[i];
        }
        #pragma unroll
        for (int o = 16; o; o >>= 1) {
            sum  += __shfl_xor_sync(0xffffffffu, sum, o);
            sum2 += __shfl_xor_sync(0xffffffffu, sum2, o);
        }
        const float m    = sum * (1.f / NC);
        const float var  = fmaxf(sum2 * (1.f / NC) - m * m, 0.f);
        const float rstd = rsqrtf(var + 1e-5f);
        #pragma unroll
        for (int i = 0; i < 8; i++) {
            const int c = lane + 32 * i;
            hs[row * HP + c] = __float2half_rn((v[i] - m) * rstd * ln1_g[c] + ln1_b[c]);
        }
    }
    __syncthreads();

    __half* outg = qkv_relay + (size_t)r0 * 768;
    #pragma unroll 1
    for (int p = 0; p < 2; p++) {
        const int nt = wq * 12 + p * 6;
        do_gemm<0, 16, 6, 4>(hs, HP, wqkv, 16, nt, 0, qkv_b, nullptr,
                             outg, nullptr, 768, nt * 8);
    }
}

// ---------------- post kernel: relay proj+LN2+MLP (64 rows/CTA, grid 128) ----------------
__global__ void __launch_bounds__(THREADS, 1)
post_kernel(const float* __restrict__ rt_in, const __half* __restrict__ attnout,
            const uint2* __restrict__ wproj, const uint2* __restrict__ w1p,
            const uint2* __restrict__ w2p,
            const float* __restrict__ proj_b,
            const float* __restrict__ ln2_g, const float* __restrict__ ln2_b,
            const float* __restrict__ b1,   const float* __restrict__ b2,
            const float* __restrict__ gamma1, const float* __restrict__ gamma2,
            float* __restrict__ out_rt)
{
    extern __shared__ char sm8[];
    float*  xs  = (float*)sm8;                               // [64][258]
    __half* hs  = (__half*)(sm8 + 64 * XP * 4);              // [64][264]
    __half* hid = (__half*)(sm8 + 64 * XP * 4 + 64 * HP * 2);// [64][520]
    const int tid = threadIdx.x, wq = tid >> 5, lane = tid & 31;
    const int r0 = blockIdx.x * 64;

    for (int idx = tid; idx < 64 * NC; idx += THREADS) {
        const int row = idx >> 8, c = idx & 255;
        xs[row * XP + c] = rt_in[(size_t)(r0 + row) * NC + c];
        hs[row * HP + c] = attnout[(size_t)(r0 + row) * NC + c];
    }
    __syncthreads();

    do_gemm<2, 16, 4, 4>(hs, HP, wproj, 16, wq * 4, 0, proj_b, gamma1,
                         nullptr, xs, XP, wq * 32);
    __syncthreads();

    for (int row = wq; row < 64; row += 8) {
        const float* rp = xs + row * XP;
        float sum = 0.f, sum2 = 0.f;
        #pragma unroll
        for (int c = lane; c < NC; c += 32) { float v = rp[c]; sum += v; sum2 += v * v; }
        #pragma unroll
        for (int o = 16; o; o >>= 1) {
            sum  += __shfl_xor_sync(0xffffffffu, sum, o);
            sum2 += __shfl_xor_sync(0xffffffffu, sum2, o);
        }
        const float m    = sum * (1.f / NC);
        const float var  = fmaxf(sum2 * (1.f / NC) - m * m, 0.f);
        const float rstd = rsqrtf(var + 1e-5f);
        #pragma unroll
        for (int c = lane; c < NC; c += 32)
            hs[row * HP + c] = __float2half_rn((rp[c] - m) * rstd * ln2_g[c] + ln2_b[c]);
    }
    __syncthreads();

    #pragma unroll 1
    for (int c = 0; c < 2; c++) {
        #pragma unroll 1
        for (int p = 0; p < 2; p++) {
            const int nt = c * 64 + wq * 8 + p * 4;
            do_gemm<1, 16, 4, 4>(hs, HP, w1p, 16, nt, 0, b1, nullptr,
                                 hid, nullptr, MP, nt * 8 - c * 512);
        }
        __syncthreads();
        do_gemm<2, 32, 4, 4>(hid, MP, w2p, 64, wq * 4, c * 32,
                             (c == 0) ? b2 : nullptr, gamma2, nullptr, xs, XP, wq * 32);
        __syncthreads();
    }

    for (int idx = tid; idx < 64 * NC; idx += THREADS) {
        const int row = idx >> 8, c = idx & 255;
        out_rt[(size_t)(r0 + row) * NC + c] = xs[row * XP + c];
    }
}

// ---------------- main fused window kernel (32 data rows, 2 CTAs / SM) ----------------
__global__ void __launch_bounds__(THREADS, 2)
hot_block_kernel(
    const float* __restrict__ in_data,
    const uint2* __restrict__ wp,     const uint2* __restrict__ w2p8,
    const float* __restrict__ rpe_t,
    const __half* __restrict__ qkv_relay, __half* __restrict__ attnout,
    const float* __restrict__ cpe_w,  const float* __restrict__ cpe_b,
    const float* __restrict__ ln1_g,  const float* __restrict__ ln1_b,
    const float* __restrict__ qkv_b,
    const float* __restrict__ proj_b,
    const float* __restrict__ ln2_g,  const float* __restrict__ ln2_b,
    const float* __restrict__ b1,     const float* __restrict__ b2,
    const float* __restrict__ gamma1, const float* __restrict__ gamma2,
    float* __restrict__ out_data)
{
    extern __shared__ char sm8[];
    float*  xs  = (float*)sm8;                          // [33][258] (row0 unused)
    __half* hs  = (__half*)(sm8 + XS_BYTES);            // [33][264] (row0 unused)
    __half* big = (__half*)(sm8 + XS_BYTES + HS_BYTES); // [33][776] qkv
    unsigned char* hid8 = (unsigned char*)big;          // fp8 hidden [32][1040B] overlays

    const int tid  = threadIdx.x;
    const int wq   = tid >> 5;
    const int lane = tid & 31;
    const int w    = blockIdx.x;

    const uint2* wqkv  = wp + WP_QKV;
    const uint2* wproj = wp + WP_PROJ;
    const uint2* w1p   = wp + WP_W1;

    // ---- Phase A: cpe + LN1 fused (data rows) + relay qkv row0 load ----
    for (int s = 1 + wq; s < SW; s += 8) {
        const long r = (long)w * KW + (s - 1);
        const float* row0 = in_data + r * NC;
        const float* rowm = (r > 0)        ? row0 - NC : nullptr;
        const float* rowp = (r < NTOK - 1) ? row0 + NC : nullptr;
        float v[8], sum = 0.f, sum2 = 0.f;
        #pragma unroll
        for (int i = 0; i < 8; i++) {
            const int c = lane + 32 * i;
            const float x0 = row0[c];
            const float xm = rowm ? rowm[c] : 0.f;
            const float xp = rowp ? rowp[c] : 0.f;
            v[i] = x0 + xm * cpe_w[c] + x0 * cpe_w[NC + c] + xp * cpe_w[2 * NC + c] + cpe_b[c];
            sum += v[i]; sum2 += v[i] * v[i];
        }
        #pragma unroll
        for (int o = 16; o; o >>= 1) {
            sum  += __shfl_xor_sync(0xffffffffu, sum, o);
            sum2 += __shfl_xor_sync(0xffffffffu, sum2, o);
        }
        const float m    = sum * (1.f / NC);
        const float var  = fmaxf(sum2 * (1.f / NC) - m * m, 0.f);
        const float rstd = rsqrtf(var + 1e-5f);
        #pragma unroll
        for (int i = 0; i < 8; i++) {
            const int c = lane + 32 * i;
            xs[s * XP + c] = v[i];
            hs[s * HP + c] = __float2half_rn((v[i] - m) * rstd * ln1_g[c] + ln1_b[c]);
        }
    }
    {   // relay qkv -> big row 0
        const unsigned* src = (const unsigned*)(qkv_relay + (size_t)w * 768);
        unsigned* dst = (unsigned*)big;
        for (int idx = tid; idx < 384; idx += THREADS) dst[idx] = src[idx];
    }
    __syncthreads();

    // ---- Phase C: qkv (data rows) -> big rows 1..32 ----
    #pragma unroll 1
    for (int p = 0; p < 2; p++) {
        const int nt = wq * 12 + p * 6;
        do_gemm<0, 16, 6, 2>(hs + HP, HP, wqkv, 16, nt, 0, qkv_b, nullptr,
                             big + BP, nullptr, BP, nt * 8);
    }
    __syncthreads();

    // ---- Phase D: attention (warp = head) ----
    {
        const int h = wq;
        const float* rpt = rpe_t + h * SW * SW;

        __half2 qh[16];
        {
            const uint4* qp = (const uint4*)(big + (1 + lane) * BP + h * ND);
            #pragma unroll
            for (int i = 0; i < 4; i++) ((uint4*)qh)[i] = qp[i];
        }
        float denom = 0.f;
        __half2 o2[16];
        #pragma unroll
        for (int i = 0; i < 16; i++) o2[i] = __floats2half2_rn(0.f, 0.f);
        #pragma unroll
        for (int k = 0; k < SW; k++) {
            __half2 kh[16], vh[16];
            const uint4* kp = (const uint4*)(big + k * BP + 256 + h * ND);
            const uint4* vp = (const uint4*)(big + k * BP + 512 + h * ND);
            #pragma unroll
            for (int i = 0; i < 4; i++) { ((uint4*)kh)[i] = kp[i]; ((uint4*)vh)[i] = vp[i]; }
            const float sv = dot32_h2(qh, kh);
            const float e  = __expf(fmaf(sv, ATT_SCALE, rpt[k * SW + lane + 1]));
            denom += e;
            const __half2 e2 = __float2half2_rn(e);
            #pragma unroll
            for (int i = 0; i < 16; i++) o2[i] = __hfma2(e2, vh[i], o2[i]);
        }
        const float inv = 1.f / denom;
        unsigned* op = (unsigned*)(hs + (1 + lane) * HP + h * ND);
        #pragma unroll
        for (int i = 0; i < 16; i++) {
            const float2 f = __half22float2(o2[i]);
            op[i] = pack2h(f.x * inv, f.y * inv);
        }

        // relay query (reference q = 0)
        __half2 q0h[16], kh[16];
        {
            const uint4* qp = (const uint4*)(big + h * ND);
            #pragma unroll
            for (int i = 0; i < 4; i++) ((uint4*)q0h)[i] = qp[i];
        }
        {
            const uint4* kp = (const uint4*)(big + lane * BP + 256 + h * ND);
            #pragma unroll
            for (int i = 0; i < 4; i++) ((uint4*)kh)[i] = kp[i];
        }
        float e = __expf(fmaf(dot32_h2(q0h, kh), ATT_SCALE, rpt[lane * SW]));
        {
            const uint4* kp = (const uint4*)(big + 32 * BP + 256 + h * ND);
            #pragma unroll
            for (int i = 0; i < 4; i++) ((uint4*)kh)[i] = kp[i];
        }
        const float e32 = __expf(fmaf(dot32_h2(q0h, kh), ATT_SCALE, rpt[32 * SW]));
        float d = e;
        #pragma unroll
        for (int o = 16; o; o >>= 1) d += __shfl_xor_sync(0xffffffffu, d, o);
        d += e32;
        const float invd = 1.f / d;
        const float p    = e * invd;
        float o = (e32 * invd) * __half2float(big[32 * BP + 512 + h * ND + lane]);
        #pragma unroll 4
        for (int k = 0; k < 32; k++) {
            const float pk = __shfl_sync(0xffffffffu, p, k);
            o = fmaf(pk, __half2float(big[k * BP + 512 + h * ND + lane]), o);
        }
        attnout[(size_t)w * NC + h * ND + lane] = __float2half_rn(o);
    }
    __syncthreads();

    // ---- Phase E: xs += gamma1 * (o @ proj_w + proj_b) ----
    do_gemm<2, 16, 4, 2>(hs + HP, HP, wproj, 16, wq * 4, 0, proj_b, gamma1,
                         nullptr, xs + XP, XP, wq * 32);
    __syncthreads();

    // ---- Phase F: LN2 (data rows) ----
    for (int s = 1 + wq; s < SW; s += 8) {
        const float* rp = xs + s * XP;
        float sum = 0.f, sum2 = 0.f;
        #pragma unroll
        for (int c = lane; c < NC; c += 32) { float v = rp[c]; sum += v; sum2 += v * v; }
        #pragma unroll
        for (int o = 16; o; o >>= 1) {
            sum  += __shfl_xor_sync(0xffffffffu, sum, o);
            sum2 += __shfl_xor_sync(0xffffffffu, sum2, o);
        }
        const float m    = sum * (1.f / NC);
        const float var  = fmaxf(sum2 * (1.f / NC) - m * m, 0.f);
        const float rstd = rsqrtf(var + 1e-5f);
        #pragma unroll
        for (int c = lane; c < NC; c += 32)
            hs[s * HP + c] = __float2half_rn((rp[c] - m) * rstd * ln2_g[c] + ln2_b[c]);
    }
    __syncthreads();

    // ---- Phase G: MLP single-pass, hidden fp8 [32][1040B] ----
    #pragma unroll 1
    for (int p = 0; p < 4; p++) {
        const int nt = wq * 16 + p * 4;     // 8 warps x 16 n8-tiles = 1024 cols
        do_gemm_gelu8<16>(hs + HP, HP, w1p, 16, nt, b1, hid8, HDB, nt * 8);
    }
    __syncthreads();
    do_gemm8<32>(hid8, HDB, w2p8, 32, wq * 4, b2, gamma2, xs + XP, XP, wq * 32);
    __syncthreads();

    // ---- Phase H: write data rows ----
    for (int idx = tid; idx < KW * NC; idx += THREADS) {
        const int s = idx >> 8, c = idx & 255;
        out_data[((size_t)w * KW + s) * NC + c] = xs[(s + 1) * XP + c];
    }
}

// ---------------- host launch ----------------
extern "C" void kernel_launch(void* const* d_in, const int* in_sizes, int n_in,
                              void* d_out, int out_size) {
    (void)in_sizes; (void)n_in; (void)out_size;
    const float* data   = (const float*)d_in[0];
    const float* rt     = (const float*)d_in[1];
    const float* cpe_w  = (const float*)d_in[2];
    const float* cpe_b  = (const float*)d_in[3];
    const float* ln1_g  = (const float*)d_in[4];
    const float* ln1_b  = (const float*)d_in[5];
    const float* qkv_w  = (const float*)d_in[6];
    const float* qkv_b  = (const float*)d_in[7];
    const float* rpe    = (const float*)d_in[8];
    const float* proj_w = (const float*)d_in[9];
    const float* proj_b = (const float*)d_in[10];
    const float* ln2_g  = (const float*)d_in[11];
    const float* ln2_b  = (const float*)d_in[12];
    const float* w1     = (const float*)d_in[13];
    const float* b1     = (const float*)d_in[14];
    const float* w2     = (const float*)d_in[15];
    const float* b2     = (const float*)d_in[16];
    const float* gamma1 = (const float*)d_in[17];
    const float* gamma2 = (const float*)d_in[18];

    float* out_data = (float*)d_out;
    float* out_rt   = out_data + (size_t)NTOK * NC;

    cudaFuncSetAttribute(hot_block_kernel,
                         cudaFuncAttributeMaxDynamicSharedMemorySize, SMEM_BYTES);
    cudaFuncSetAttribute(pre_kernel,
                         cudaFuncAttributeMaxDynamicSharedMemorySize, PRE_SMEM);
    cudaFuncSetAttribute(post_kernel,
                         cudaFuncAttributeMaxDynamicSharedMemorySize, POST_SMEM);

    float *bd, *brt, *rpt;
    cudaGetSymbolAddress((void**)&bd,  g_buf_data);
    cudaGetSymbolAddress((void**)&brt, g_buf_rt);
    cudaGetSymbolAddress((void**)&rpt, g_rpe_t);
    uint2 *wpall, *w2p8;
    cudaGetSymbolAddress((void**)&wpall, g_wperm);
    cudaGetSymbolAddress((void**)&w2p8,  g_w2p8);
    __half *qkvr, *attn;
    cudaGetSymbolAddress((void**)&qkvr, g_qkv_relay);
    cudaGetSymbolAddress((void**)&attn, g_attnout);

    // 8 launches/call: [convert, marker, pre0, main0, post0, pre1, main1, post1]
    // -> ncu abs launch idx 3 = main0
    {
        int tot = 2 * WP_BLK + 2 * W2P8_BLK + 2 * NH * SW * SW;
        convert_all_kernel<<<(tot + 255) / 256, 256>>>(
            qkv_w, proj_w, w1, w2, rpe, wpall, w2p8, rpt);
    }
    marker_kernel<<<1, 32>>>();

    for (int blk = 0; blk < 2; blk++) {
        const uint2* wpb  = wpall + (size_t)blk * WP_BLK;
        const uint2* w2pb = w2p8  + (size_t)blk * W2P8_BLK;
        const float* rtin  = (blk == 0) ? rt : brt;
        const float* din   = (blk == 0) ? data : bd;
        float*       dout  = (blk == 0) ? bd : out_data;
        float*       rtout = (blk == 0) ? brt : out_rt;
        const int o1 = blk * NC, o3 = blk * 3 * NC, oh = blk * NHID;

        pre_kernel<<<128, THREADS, PRE_SMEM>>>(
            rtin, wpb + WP_QKV, ln1_g + o1, ln1_b + o1, qkv_b + o3, qkvr);

        hot_block_kernel<<<NWIN, THREADS, SMEM_BYTES>>>(
            din, wpb, w2pb, rpt + blk * NH * SW * SW, qkvr, attn,
            cpe_w + blk * 3 * NC, cpe_b + o1, ln1_g + o1, ln1_b + o1,
            qkv_b + o3, proj_b + o1, ln2_g + o1, ln2_b + o1,
            b1 + oh, b2 + o1, gamma1 + o1, gamma2 + o1, dout);

        post_kernel<<<128, THREADS, POST_SMEM>>>(
            rtin, attn, wpb + WP_PROJ, wpb + WP_W1, wpb + WP_W2,
            proj_b + o1, ln2_g + o1, ln2_b + o1, b1 + oh, b2 + o1,
            gamma1 + o1, gamma2 + o1, rtout);
    }
}

// round 13
// speedup vs baseline: 1.6819x; 1.0705x over previous
#include <cuda_runtime.h>
#include <cuda_fp16.h>
#include <cuda_fp8.h>
#include <math.h>

// ---------------- problem constants ----------------
#define NC    256
#define NH    8
#define ND    32
#define KW    32
#define SW    33
#define NWIN  8192
#define NTOK  (NWIN*KW)
#define NHID  1024
#define ATT_SCALE 0.17677669529663687f
#define THREADS 256
#define WSCALE 64.0f
#define INVWS  0.015625f

// ---------------- smem pitches ----------------
#define XP  258    // xs fp32 pitch (elements)
#define HP  264    // hs fp16 pitch (elements)
#define BP  776    // qkv fp16 pitch (elements; 33 rows, row0 = relay)
#define MP  520    // post-kernel mlp hidden fp16 pitch (elements)
#define HDB 1040   // main-kernel mlp hidden fp8 pitch (BYTES)

#define XS_BYTES   34080
#define HS_BYTES   (33*HP*2)             // 17424
#define BIG_BYTES  (33*BP*2)             // 51216
#define SMEM_BYTES (XS_BYTES + HS_BYTES + BIG_BYTES)   // 102720 -> 2 CTA/SM

#define PRE_SMEM   (64*HP*2)
#define POST_SMEM  (64*XP*4 + 64*HP*2 + 64*MP*2)

// ---------------- global scratch ----------------
__device__ float  g_buf_data[(size_t)NTOK * NC];
__device__ float  g_buf_rt[(size_t)NWIN * NC];
__device__ __half g_qkv_relay[(size_t)NWIN * 768];
__device__ __half g_attnout[(size_t)NWIN * NC];

// fp16 permuted weight B-fragments, per block (uint2 counts):
#define WP_QKV  0
#define WP_PROJ 49152
#define WP_W1   65536
#define WP_W2   131072
#define WP_BLK  196608
__device__ uint2 g_wperm[2 * WP_BLK];

// fp8 w2 B-fragments (k32), per block
#define W2P8_BLK 32768
__device__ uint2 g_w2p8[2 * W2P8_BLK];

// rpe in mma-C-fragment layout: [blk][h][mt(2)][nt(5)][lane(32)] float4
#define RPEF_BLK 2560
__device__ float4 g_rpef[2 * RPEF_BLK];

// ---------------- helpers ----------------
__device__ __forceinline__ unsigned sm_u32(const void* p) {
    return (unsigned)__cvta_generic_to_shared(p);
}
__device__ __forceinline__ unsigned pack2h(float a, float b) {
    __half2 h = __floats2half2_rn(a, b);
    return *reinterpret_cast<unsigned*>(&h);
}
__device__ __forceinline__ unsigned char to_fp8(float x) {
    return (unsigned char)__nv_cvt_float_to_fp8(x, __NV_SATFINITE, __NV_E4M3);
}
__device__ __forceinline__ unsigned short to_fp8x2(float x, float y) {
    float2 f = make_float2(x, y);
    return (unsigned short)__nv_cvt_float2_to_fp8x2(f, __NV_SATFINITE, __NV_E4M3);
}
__device__ __forceinline__ float gelu_tanh(float x) {
    float t = 0.7978845608028654f * (x + 0.044715f * x * x * x);
    float th;
    asm("tanh.approx.f32 %0, %1;" : "=f"(th) : "f"(t));
    return 0.5f * x * (1.f + th);
}
__device__ __forceinline__ void ldmat4(unsigned a[4], unsigned addr) {
    asm volatile("ldmatrix.sync.aligned.m8n8.x4.shared.b16 {%0,%1,%2,%3}, [%4];"
                 : "=r"(a[0]), "=r"(a[1]), "=r"(a[2]), "=r"(a[3]) : "r"(addr));
}
__device__ __forceinline__ void ldmat2(unsigned& b0, unsigned& b1, unsigned addr) {
    asm volatile("ldmatrix.sync.aligned.m8n8.x2.shared.b16 {%0,%1}, [%2];"
                 : "=r"(b0), "=r"(b1) : "r"(addr));
}
__device__ __forceinline__ void ldmat2t(unsigned& b0, unsigned& b1, unsigned addr) {
    asm volatile("ldmatrix.sync.aligned.m8n8.x2.trans.shared.b16 {%0,%1}, [%2];"
                 : "=r"(b0), "=r"(b1) : "r"(addr));
}
__device__ __forceinline__ void mma_f16(float c[4], const unsigned a[4], const uint2 b) {
    asm volatile("mma.sync.aligned.m16n8k16.row.col.f32.f16.f16.f32 "
                 "{%0,%1,%2,%3},{%4,%5,%6,%7},{%8,%9},{%0,%1,%2,%3};"
                 : "+f"(c[0]), "+f"(c[1]), "+f"(c[2]), "+f"(c[3])
                 : "r"(a[0]), "r"(a[1]), "r"(a[2]), "r"(a[3]), "r"(b.x), "r"(b.y));
}
__device__ __forceinline__ void mma_fp8(float c[4], const unsigned a[4], const uint2 b) {
    asm volatile("mma.sync.aligned.m16n8k32.row.col.f32.e4m3.e4m3.f32 "
                 "{%0,%1,%2,%3},{%4,%5,%6,%7},{%8,%9},{%0,%1,%2,%3};"
                 : "+f"(c[0]), "+f"(c[1]), "+f"(c[2]), "+f"(c[3])
                 : "r"(a[0]), "r"(a[1]), "r"(a[2]), "r"(a[3]), "r"(b.x), "r"(b.y));
}

// ---------------- fused conversion kernel ----------------
__global__ void convert_all_kernel(const float* __restrict__ qkv_w,
                                   const float* __restrict__ proj_w,
                                   const float* __restrict__ w1,
                                   const float* __restrict__ w2,
                                   const float* __restrict__ rpe,
                                   uint2* __restrict__ out16,
                                   uint2* __restrict__ out8,
                                   float4* __restrict__ rpef) {
    const int N16 = 2 * WP_BLK, N8 = 2 * W2P8_BLK, NRF = 2 * RPEF_BLK;
    int idx = blockIdx.x * blockDim.x + threadIdx.x;
    if (idx < N16) {
        const int blk = idx / WP_BLK;
        int r = idx - blk * WP_BLK;
        const float* W; int K, N; int local;
        if (r < WP_PROJ)      { W = qkv_w  + (size_t)blk * 256 * 768;  K = 256;  N = 768;  local = r; }
        else if (r < WP_W1)   { W = proj_w + (size_t)blk * 256 * 256;  K = 256;  N = 256;  local = r - WP_PROJ; }
        else if (r < WP_W2)   { W = w1     + (size_t)blk * 256 * 1024; K = 256;  N = 1024; local = r - WP_W1; }
        else                  { W = w2     + (size_t)blk * 1024 * 256; K = 1024; N = 256;  local = r - WP_W2; }
        const int lane = local & 31;
        const int t    = local >> 5;
        const int KT   = K / 16;
        const int kt   = t % KT, nt = t / KT;
        const int n    = nt * 8 + (lane >> 2);
        const int k0   = kt * 16 + (lane & 3) * 2;
        out16[idx] = make_uint2(
            pack2h(W[(size_t)k0 * N + n],       W[(size_t)(k0 + 1) * N + n]),
            pack2h(W[(size_t)(k0 + 8) * N + n], W[(size_t)(k0 + 9) * N + n]));
    } else if (idx < N16 + N8) {
        int j = idx - N16;
        const int blk = j / W2P8_BLK;
        int local = j - blk * W2P8_BLK;
        const float* W = w2 + (size_t)blk * 1024 * 256;
        const int lane = local & 31;
        const int t    = local >> 5;
        const int KT   = 32;
        const int kt   = t % KT, nt = t / KT;
        const int n    = nt * 8 + (lane >> 2);
        const int k0   = kt * 32 + (lane & 3) * 4;
        unsigned lo = 0, hi = 0;
        #pragma unroll
        for (int i = 0; i < 4; i++) {
            lo |= (unsigned)to_fp8(W[(size_t)(k0 + i)      * 256 + n] * WSCALE) << (8 * i);
            hi |= (unsigned)to_fp8(W[(size_t)(k0 + 16 + i) * 256 + n] * WSCALE) << (8 * i);
        }
        out8[j] = make_uint2(lo, hi);
    } else if (idx < N16 + N8 + NRF) {
        int j = idx - N16 - N8;
        const int blk  = j / RPEF_BLK;
        int rem  = j - blk * RPEF_BLK;            // [h][mt][nt][lane]
        const int h    = rem / 320;
        rem  = rem - h * 320;
        const int mt   = rem / 160;
        const int nt   = (rem % 160) / 32;
        const int lane = rem & 31;
        const int rr   = lane >> 2, cq = (lane & 3) * 2;
        const int q0   = mt * 16 + rr + 1, q1 = q0 + 8;   // data queries (ref q)
        const int k0   = nt * 8 + cq,      k1 = k0 + 1;   // keys (ref k)
        const float* rh = rpe + ((size_t)blk * NH + h) * SW * SW;
        float4 v;
        v.x = (k0 <= 32) ? rh[q0 * SW + k0] : 0.f;
        v.y = (k1 <= 32) ? rh[q0 * SW + k1] : 0.f;
        v.z = (k0 <= 32) ? rh[q1 * SW + k0] : 0.f;
        v.w = (k1 <= 32) ? rh[q1 * SW + k1] : 0.f;
        rpef[j] = v;
    }
}

// one marker so ncu's profiled launch (abs idx 3) = main kernel block 0
__global__ void marker_kernel() {}

// ---------------- fp16 k-outer GEMM (MT m-tiles x NT n8-tiles / warp) ----------------
template<int MODE, int KSTEPS, int NT, int MT>
__device__ __forceinline__ void do_gemm(
    const __half* __restrict__ Ash, int apitch,
    const uint2* __restrict__ wmat, int KTtot, int nt0, int kt0,
    const float* __restrict__ bias, const float* __restrict__ gvec,
    __half* __restrict__ outh, float* __restrict__ outf,
    int opitch, int ocol0)
{
    const int lane = threadIdx.x & 31;
    float acc[MT][NT][4];
    #pragma unroll
    for (int mt = 0; mt < MT; mt++)
        #pragma unroll
        for (int j = 0; j < NT; j++)
            #pragma unroll
            for (int e = 0; e < 4; e++) acc[mt][j][e] = 0.f;

    unsigned abase[MT];
    #pragma unroll
    for (int mt = 0; mt < MT; mt++) {
        int row = mt * 16 + (lane & 15);
        abase[mt] = sm_u32(Ash + row * apitch + ((lane >> 4) << 3));
    }
    const uint2* wb = wmat + ((size_t)nt0 * KTtot + kt0) * 32 + lane;

    #pragma unroll 4
    for (int kt = 0; kt < KSTEPS; kt++) {
        uint2 b[NT];
        #pragma unroll
        for (int j = 0; j < NT; j++) b[j] = __ldg(wb + ((size_t)j * KTtot + kt) * 32);
        unsigned a[MT][4];
        #pragma unroll
        for (int mt = 0; mt < MT; mt++) ldmat4(a[mt], abase[mt] + (unsigned)(kt * 32));
        #pragma unroll
        for (int mt = 0; mt < MT; mt++)
            #pragma unroll
            for (int j = 0; j < NT; j++) mma_f16(acc[mt][j], a[mt], b[j]);
    }

    const int cq = (lane & 3) * 2;
    const int rr = lane >> 2;
    #pragma unroll
    for (int j = 0; j < NT; j++) {
        const int mcol = (nt0 + j) * 8 + cq;
        const int ocol = ocol0 + j * 8 + cq;
        float b0s = 0.f, b1s = 0.f;
        if (bias) { b0s = bias[mcol]; b1s = bias[mcol + 1]; }
        float g0 = 0.f, g1 = 0.f;
        if (MODE == 2) { g0 = gvec[ocol]; g1 = gvec[ocol + 1]; }
        #pragma unroll
        for (int mt = 0; mt < MT; mt++) {
            const int r0 = mt * 16 + rr, r1 = r0 + 8;
            const float* a4 = acc[mt][j];
            const float v00 = a4[0] + b0s, v01 = a4[1] + b1s;
            const float v10 = a4[2] + b0s, v11 = a4[3] + b1s;
            if (MODE == 0) {
                *(unsigned*)(outh + r0 * opitch + ocol) = pack2h(v00, v01);
                *(unsigned*)(outh + r1 * opitch + ocol) = pack2h(v10, v11);
            } else if (MODE == 1) {
                *(unsigned*)(outh + r0 * opitch + ocol) = pack2h(gelu_tanh(v00), gelu_tanh(v01));
                *(unsigned*)(outh + r1 * opitch + ocol) = pack2h(gelu_tanh(v10), gelu_tanh(v11));
            } else {
                float* p0 = outf + r0 * opitch + ocol;
                p0[0] += g0 * v00; p0[1] += g1 * v01;
                float* p1 = outf + r1 * opitch + ocol;
                p1[0] += g0 * v10; p1[1] += g1 * v11;
            }
        }
    }
}

// ---------------- w1 GEMM: fp16 mma, gelu -> fp8 packed (MT=2, template NT) ----------------
template<int KSTEPS, int NT>
__device__ __forceinline__ void do_gemm_gelu8(
    const __half* __restrict__ Ash, int apitch,
    const uint2* __restrict__ wmat, int KTtot, int nt0,
    const float* __restrict__ bias,
    unsigned char* __restrict__ out8, int opitchB, int ocol0)
{
    const int lane = threadIdx.x & 31;
    float acc[2][NT][4];
    #pragma unroll
    for (int mt = 0; mt < 2; mt++)
        #pragma unroll
        for (int j = 0; j < NT; j++)
            #pragma unroll
            for (int e = 0; e < 4; e++) acc[mt][j][e] = 0.f;

    unsigned abase[2];
    #pragma unroll
    for (int mt = 0; mt < 2; mt++) {
        int row = mt * 16 + (lane & 15);
        abase[mt] = sm_u32(Ash + row * apitch + ((lane >> 4) << 3));
    }
    const uint2* wb = wmat + (size_t)nt0 * KTtot * 32 + lane;

    #pragma unroll 4
    for (int kt = 0; kt < KSTEPS; kt++) {
        uint2 b[NT];
        #pragma unroll
        for (int j = 0; j < NT; j++) b[j] = __ldg(wb + ((size_t)j * KTtot + kt) * 32);
        unsigned a[2][4];
        #pragma unroll
        for (int mt = 0; mt < 2; mt++) ldmat4(a[mt], abase[mt] + (unsigned)(kt * 32));
        #pragma unroll
        for (int mt = 0; mt < 2; mt++)
            #pragma unroll
            for (int j = 0; j < NT; j++) mma_f16(acc[mt][j], a[mt], b[j]);
    }

    const int cq = (lane & 3) * 2;
    const int rr = lane >> 2;
    #pragma unroll
    for (int j = 0; j < NT; j++) {
        const int mcol = (nt0 + j) * 8 + cq;
        const int ocol = ocol0 + j * 8 + cq;
        const float b0s = bias[mcol], b1s = bias[mcol + 1];
        #pragma unroll
        for (int mt = 0; mt < 2; mt++) {
            const int r0 = mt * 16 + rr, r1 = r0 + 8;
            const float* a4 = acc[mt][j];
            *(unsigned short*)(out8 + r0 * opitchB + ocol) =
                to_fp8x2(gelu_tanh(a4[0] + b0s), gelu_tanh(a4[1] + b1s));
            *(unsigned short*)(out8 + r1 * opitchB + ocol) =
                to_fp8x2(gelu_tanh(a4[2] + b0s), gelu_tanh(a4[3] + b1s));
        }
    }
}

// ---------------- w2 GEMM: fp8 x fp8 (k32), residual epilogue (MT=2, NT=4) ----------------
template<int KSTEPS>
__device__ __forceinline__ void do_gemm8(
    const unsigned char* __restrict__ Ash, int apitchB,
    const uint2* __restrict__ wmat, int KTtot, int nt0,
    const float* __restrict__ bias, const float* __restrict__ gvec,
    float* __restrict__ outf, int opitch, int ocol0)
{
    const int lane = threadIdx.x & 31;
    float acc[2][4][4];
    #pragma unroll
    for (int mt = 0; mt < 2; mt++)
        #pragma unroll
        for (int j = 0; j < 4; j++)
            #pragma unroll
            for (int e = 0; e < 4; e++) acc[mt][j][e] = 0.f;

    unsigned abase[2];
    #pragma unroll
    for (int mt = 0; mt < 2; mt++) {
        int row = mt * 16 + (lane & 15);
        abase[mt] = sm_u32(Ash + row * apitchB + ((lane >> 4) << 4));
    }
    const uint2* wb = wmat + (size_t)nt0 * KTtot * 32 + lane;

    #pragma unroll 4
    for (int kt = 0; kt < KSTEPS; kt++) {
        uint2 b[4];
        #pragma unroll
        for (int j = 0; j < 4; j++) b[j] = __ldg(wb + ((size_t)j * KTtot + kt) * 32);
        unsigned a[2][4];
        #pragma unroll
        for (int mt = 0; mt < 2; mt++) ldmat4(a[mt], abase[mt] + (unsigned)(kt * 32));
        #pragma unroll
        for (int mt = 0; mt < 2; mt++)
            #pragma unroll
            for (int j = 0; j < 4; j++) mma_fp8(acc[mt][j], a[mt], b[j]);
    }

    const int cq = (lane & 3) * 2;
    const int rr = lane >> 2;
    #pragma unroll
    for (int j = 0; j < 4; j++) {
        const int mcol = (nt0 + j) * 8 + cq;
        const int ocol = ocol0 + j * 8 + cq;
        const float b0s = bias[mcol], b1s = bias[mcol + 1];
        const float g0 = gvec[ocol], g1 = gvec[ocol + 1];
        #pragma unroll
        for (int mt = 0; mt < 2; mt++) {
            const int r0 = mt * 16 + rr, r1 = r0 + 8;
            const float* a4 = acc[mt][j];
            float* p0 = outf + r0 * opitch + ocol;
            p0[0] += g0 * fmaf(a4[0], INVWS, b0s);
            p0[1] += g1 * fmaf(a4[1], INVWS, b1s);
            float* p1 = outf + r1 * opitch + ocol;
            p1[0] += g0 * fmaf(a4[2], INVWS, b0s);
            p1[1] += g1 * fmaf(a4[3], INVWS, b1s);
        }
    }
}

// hfma2 dot: 16 half2 pairs -> fp32 scalar (relay path)
__device__ __forceinline__ float dot32_h2(const __half2* a, const __half2* b) {
    __half2 acc0 = __hmul2(a[0], b[0]);
    __half2 acc1 = __hmul2(a[1], b[1]);
    #pragma unroll
    for (int i = 2; i < 16; i += 2) {
        acc0 = __hfma2(a[i],     b[i],     acc0);
        acc1 = __hfma2(a[i + 1], b[i + 1], acc1);
    }
    __half2 acc = __hadd2(acc0, acc1);
    return __half2float(__low2half(acc)) + __half2float(__high2half(acc));
}

// ---------------- pre kernel: relay LN1 + qkv ----------------
__global__ void __launch_bounds__(THREADS, 1)
pre_kernel(const float* __restrict__ rt_in, const uint2* __restrict__ wqkv,
           const float* __restrict__ ln1_g, const float* __restrict__ ln1_b,
           const float* __restrict__ qkv_b, __half* __restrict__ qkv_relay)
{
    extern __shared__ char sm8[];
    __half* hs = (__half*)sm8;
    const int tid = threadIdx.x, wq = tid >> 5, lane = tid & 31;
    const int r0 = blockIdx.x * 64;

    for (int row = wq; row < 64; row += 8) {
        const float* rp = rt_in + (size_t)(r0 + row) * NC;
        float v[8], sum = 0.f, sum2 = 0.f;
        #pragma unroll
        for (int i = 0; i < 8; i++) {
            v[i] = rp[lane + 32 * i];
            sum += v[i]; sum2 += v[i] * v[i];
        }
        #pragma unroll
        for (int o = 16; o; o >>= 1) {
            sum  += __shfl_xor_sync(0xffffffffu, sum, o);
            sum2 += __shfl_xor_sync(0xffffffffu, sum2, o);
        }
        const float m    = sum * (1.f / NC);
        const float var  = fmaxf(sum2 * (1.f / NC) - m * m, 0.f);
        const float rstd = rsqrtf(var + 1e-5f);
        #pragma unroll
        for (int i = 0; i < 8; i++) {
            const int c = lane + 32 * i;
            hs[row * HP + c] = __float2half_rn((v[i] - m) * rstd * ln1_g[c] + ln1_b[c]);
        }
    }
    __syncthreads();

    __half* outg = qkv_relay + (size_t)r0 * 768;
    #pragma unroll 1
    for (int p = 0; p < 2; p++) {
        const int nt = wq * 12 + p * 6;
        do_gemm<0, 16, 6, 4>(hs, HP, wqkv, 16, nt, 0, qkv_b, nullptr,
                             outg, nullptr, 768, nt * 8);
    }
}

// ---------------- post kernel: relay proj+LN2+MLP ----------------
__global__ void __launch_bounds__(THREADS, 1)
post_kernel(const float* __restrict__ rt_in, const __half* __restrict__ attnout,
            const uint2* __restrict__ wproj, const uint2* __restrict__ w1p,
            const uint2* __restrict__ w2p,
            const float* __restrict__ proj_b,
            const float* __restrict__ ln2_g, const float* __restrict__ ln2_b,
            const float* __restrict__ b1,   const float* __restrict__ b2,
            const float* __restrict__ gamma1, const float* __restrict__ gamma2,
            float* __restrict__ out_rt)
{
    extern __shared__ char sm8[];
    float*  xs  = (float*)sm8;
    __half* hs  = (__half*)(sm8 + 64 * XP * 4);
    __half* hid = (__half*)(sm8 + 64 * XP * 4 + 64 * HP * 2);
    const int tid = threadIdx.x, wq = tid >> 5, lane = tid & 31;
    const int r0 = blockIdx.x * 64;

    for (int idx = tid; idx < 64 * NC; idx += THREADS) {
        const int row = idx >> 8, c = idx & 255;
        xs[row * XP + c] = rt_in[(size_t)(r0 + row) * NC + c];
        hs[row * HP + c] = attnout[(size_t)(r0 + row) * NC + c];
    }
    __syncthreads();

    do_gemm<2, 16, 4, 4>(hs, HP, wproj, 16, wq * 4, 0, proj_b, gamma1,
                         nullptr, xs, XP, wq * 32);
    __syncthreads();

    for (int row = wq; row < 64; row += 8) {
        const float* rp = xs + row * XP;
        float sum = 0.f, sum2 = 0.f;
        #pragma unroll
        for (int c = lane; c < NC; c += 32) { float v = rp[c]; sum += v; sum2 += v * v; }
        #pragma unroll
        for (int o = 16; o; o >>= 1) {
            sum  += __shfl_xor_sync(0xffffffffu, sum, o);
            sum2 += __shfl_xor_sync(0xffffffffu, sum2, o);
        }
        const float m    = sum * (1.f / NC);
        const float var  = fmaxf(sum2 * (1.f / NC) - m * m, 0.f);
        const float rstd = rsqrtf(var + 1e-5f);
        #pragma unroll
        for (int c = lane; c < NC; c += 32)
            hs[row * HP + c] = __float2half_rn((rp[c] - m) * rstd * ln2_g[c] + ln2_b[c]);
    }
    __syncthreads();

    #pragma unroll 1
    for (int c = 0; c < 2; c++) {
        #pragma unroll 1
        for (int p = 0; p < 2; p++) {
            const int nt = c * 64 + wq * 8 + p * 4;
            do_gemm<1, 16, 4, 4>(hs, HP, w1p, 16, nt, 0, b1, nullptr,
                                 hid, nullptr, MP, nt * 8 - c * 512);
        }
        __syncthreads();
        do_gemm<2, 32, 4, 4>(hid, MP, w2p, 64, wq * 4, c * 32,
                             (c == 0) ? b2 : nullptr, gamma2, nullptr, xs, XP, wq * 32);
        __syncthreads();
    }

    for (int idx = tid; idx < 64 * NC; idx += THREADS) {
        const int row = idx >> 8, c = idx & 255;
        out_rt[(size_t)(r0 + row) * NC + c] = xs[row * XP + c];
    }
}

// ---------------- main fused window kernel (32 data rows, 2 CTAs / SM) ----------------
__global__ void __launch_bounds__(THREADS, 2)
hot_block_kernel(
    const float* __restrict__ in_data,
    const uint2* __restrict__ wp,     const uint2* __restrict__ w2p8,
    const float4* __restrict__ rpef,  const float* __restrict__ rpe0,
    const __half* __restrict__ qkv_relay, __half* __restrict__ attnout,
    const float* __restrict__ cpe_w,  const float* __restrict__ cpe_b,
    const float* __restrict__ ln1_g,  const float* __restrict__ ln1_b,
    const float* __restrict__ qkv_b,
    const float* __restrict__ proj_b,
    const float* __restrict__ ln2_g,  const float* __restrict__ ln2_b,
    const float* __restrict__ b1,     const float* __restrict__ b2,
    const float* __restrict__ gamma1, const float* __restrict__ gamma2,
    float* __restrict__ out_data)
{
    extern __shared__ char sm8[];
    float*  xs  = (float*)sm8;                          // [33][258] (row0 unused)
    __half* hs  = (__half*)(sm8 + XS_BYTES);            // [33][264] (row0 unused)
    __half* big = (__half*)(sm8 + XS_BYTES + HS_BYTES); // [33][776] qkv
    unsigned char* hid8 = (unsigned char*)big;          // fp8 hidden [32][1040B] overlays

    const int tid  = threadIdx.x;
    const int wq   = tid >> 5;
    const int lane = tid & 31;
    const int w    = blockIdx.x;

    const uint2* wqkv  = wp + WP_QKV;
    const uint2* wproj = wp + WP_PROJ;
    const uint2* w1p   = wp + WP_W1;

    // ---- Phase A: cpe + LN1 fused (data rows) + relay qkv row0 load ----
    for (int s = 1 + wq; s < SW; s += 8) {
        const long r = (long)w * KW + (s - 1);
        const float* row0 = in_data + r * NC;
        const float* rowm = (r > 0)        ? row0 - NC : nullptr;
        const float* rowp = (r < NTOK - 1) ? row0 + NC : nullptr;
        float v[8], sum = 0.f, sum2 = 0.f;
        #pragma unroll
        for (int i = 0; i < 8; i++) {
            const int c = lane + 32 * i;
            const float x0 = row0[c];
            const float xm = rowm ? rowm[c] : 0.f;
            const float xp = rowp ? rowp[c] : 0.f;
            v[i] = x0 + xm * cpe_w[c] + x0 * cpe_w[NC + c] + xp * cpe_w[2 * NC + c] + cpe_b[c];
            sum += v[i]; sum2 += v[i] * v[i];
        }
        #pragma unroll
        for (int o = 16; o; o >>= 1) {
            sum  += __shfl_xor_sync(0xffffffffu, sum, o);
            sum2 += __shfl_xor_sync(0xffffffffu, sum2, o);
        }
        const float m    = sum * (1.f / NC);
        const float var  = fmaxf(sum2 * (1.f / NC) - m * m, 0.f);
        const float rstd = rsqrtf(var + 1e-5f);
        #pragma unroll
        for (int i = 0; i < 8; i++) {
            const int c = lane + 32 * i;
            xs[s * XP + c] = v[i];
            hs[s * HP + c] = __float2half_rn((v[i] - m) * rstd * ln1_g[c] + ln1_b[c]);
        }
    }
    {   // relay qkv -> big row 0
        const unsigned* src = (const unsigned*)(qkv_relay + (size_t)w * 768);
        unsigned* dst = (unsigned*)big;
        for (int idx = tid; idx < 384; idx += THREADS) dst[idx] = src[idx];
    }
    __syncthreads();

    // ---- Phase C: qkv (data rows) -> big rows 1..32 ----
    #pragma unroll 1
    for (int p = 0; p < 2; p++) {
        const int nt = wq * 12 + p * 6;
        do_gemm<0, 16, 6, 2>(hs + HP, HP, wqkv, 16, nt, 0, qkv_b, nullptr,
                             big + BP, nullptr, BP, nt * 8);
    }
    __syncthreads();

    // ---- Phase D: attention via tensor cores (warp = head) ----
    {
        const int h  = wq;
        const int rr = lane >> 2, cq = (lane & 3) * 2;
        const int L  = lane & 15;

        // K B-fragments: K stored [key][d] == B [n][k] pattern -> plain ldmatrix
        uint2 bk[5][2];
        #pragma unroll
        for (int nt = 0; nt < 5; nt++) {
            int key = nt * 8 + (L & 7); if (key > 32) key = 32;
            #pragma unroll
            for (int kt = 0; kt < 2; kt++)
                ldmat2(bk[nt][kt].x, bk[nt][kt].y,
                       sm_u32(big + key * BP + 256 + h * ND + kt * 16 + ((L >> 3) << 3)));
        }

        // QK^T
        float accS[2][5][4];
        #pragma unroll
        for (int mt = 0; mt < 2; mt++)
            #pragma unroll
            for (int nt = 0; nt < 5; nt++)
                #pragma unroll
                for (int e = 0; e < 4; e++) accS[mt][nt][e] = 0.f;
        #pragma unroll
        for (int mt = 0; mt < 2; mt++) {
            #pragma unroll
            for (int kt = 0; kt < 2; kt++) {
                unsigned aq[4];
                ldmat4(aq, sm_u32(big + (1 + mt * 16 + L) * BP + h * ND
                                  + ((lane >> 4) << 3) + kt * 16));
                #pragma unroll
                for (int nt = 0; nt < 5; nt++) mma_f16(accS[mt][nt], aq, bk[nt][kt]);
            }
        }

        // exp + row sums + pack P as PV A-fragments (normalization deferred)
        const float4* rpef_h = rpef + h * 320;
        float sum0[2], sum1[2];
        unsigned ap[2][3][4];
        #pragma unroll
        for (int mt = 0; mt < 2; mt++) {
            float p[5][4];
            float s0 = 0.f, s1 = 0.f;
            #pragma unroll
            for (int nt = 0; nt < 5; nt++) {
                const float4 rv = rpef_h[(mt * 5 + nt) * 32 + lane];
                float e0 = __expf(fmaf(accS[mt][nt][0], ATT_SCALE, rv.x));
                float e1 = __expf(fmaf(accS[mt][nt][1], ATT_SCALE, rv.y));
                float e2 = __expf(fmaf(accS[mt][nt][2], ATT_SCALE, rv.z));
                float e3 = __expf(fmaf(accS[mt][nt][3], ATT_SCALE, rv.w));
                if (nt == 4) {                       // keys 32..39: only key 32 valid
                    const bool vld = (cq == 0);
                    e0 = vld ? e0 : 0.f; e2 = vld ? e2 : 0.f;
                    e1 = 0.f; e3 = 0.f;
                }
                p[nt][0] = e0; p[nt][1] = e1; p[nt][2] = e2; p[nt][3] = e3;
                s0 += e0 + e1; s1 += e2 + e3;
            }
            s0 += __shfl_xor_sync(0xffffffffu, s0, 1);
            s0 += __shfl_xor_sync(0xffffffffu, s0, 2);
            s1 += __shfl_xor_sync(0xffffffffu, s1, 1);
            s1 += __shfl_xor_sync(0xffffffffu, s1, 2);
            sum0[mt] = s0; sum1[mt] = s1;
            #pragma unroll
            for (int s = 0; s < 3; s++) {
                const int n0 = 2 * s, n1 = 2 * s + 1;
                ap[mt][s][0] = pack2h(p[n0][0], p[n0][1]);
                ap[mt][s][1] = pack2h(p[n0][2], p[n0][3]);
                ap[mt][s][2] = (n1 < 5) ? pack2h(p[n1][0], p[n1][1]) : 0u;
                ap[mt][s][3] = (n1 < 5) ? pack2h(p[n1][2], p[n1][3]) : 0u;
            }
        }

        // PV: V [key][d] -> B via ldmatrix.trans
        float accO[2][4][4];
        #pragma unroll
        for (int mt = 0; mt < 2; mt++)
            #pragma unroll
            for (int nt = 0; nt < 4; nt++)
                #pragma unroll
                for (int e = 0; e < 4; e++) accO[mt][nt][e] = 0.f;
        #pragma unroll
        for (int kt = 0; kt < 3; kt++) {
            int key = kt * 16 + L; if (key > 32) key = 32;
            uint2 bv[4];
            #pragma unroll
            for (int nt = 0; nt < 4; nt++)
                ldmat2t(bv[nt].x, bv[nt].y,
                        sm_u32(big + key * BP + 512 + h * ND + nt * 8));
            #pragma unroll
            for (int mt = 0; mt < 2; mt++)
                #pragma unroll
                for (int nt = 0; nt < 4; nt++) mma_f16(accO[mt][nt], ap[mt][kt], bv[nt]);
        }

        // normalize + store to hs rows 1..32 (proj A-operand)
        #pragma unroll
        for (int mt = 0; mt < 2; mt++) {
            const float i0 = 1.f / sum0[mt], i1 = 1.f / sum1[mt];
            #pragma unroll
            for (int nt = 0; nt < 4; nt++) {
                const int d = nt * 8 + cq;
                *(unsigned*)(hs + (1 + mt * 16 + rr) * HP + h * ND + d) =
                    pack2h(accO[mt][nt][0] * i0, accO[mt][nt][1] * i0);
                *(unsigned*)(hs + (9 + mt * 16 + rr) * HP + h * ND + d) =
                    pack2h(accO[mt][nt][2] * i1, accO[mt][nt][3] * i1);
            }
        }

        // relay query (ref q = 0): scalar path, rpe row [h][0][k] is coalesced
        const float* rp0 = rpe0 + h * SW * SW;
        __half2 q0h[16], kh[16];
        {
            const uint4* qp = (const uint4*)(big + h * ND);
            #pragma unroll
            for (int i = 0; i < 4; i++) ((uint4*)q0h)[i] = qp[i];
        }
        {
            const uint4* kp = (const uint4*)(big + lane * BP + 256 + h * ND);
            #pragma unroll
            for (int i = 0; i < 4; i++) ((uint4*)kh)[i] = kp[i];
        }
        float e = __expf(fmaf(dot32_h2(q0h, kh), ATT_SCALE, rp0[lane]));
        {
            const uint4* kp = (const uint4*)(big + 32 * BP + 256 + h * ND);
            #pragma unroll
            for (int i = 0; i < 4; i++) ((uint4*)kh)[i] = kp[i];
        }
        const float e32 = __expf(fmaf(dot32_h2(q0h, kh), ATT_SCALE, rp0[32]));
        float d = e;
        #pragma unroll
        for (int o = 16; o; o >>= 1) d += __shfl_xor_sync(0xffffffffu, d, o);
        d += e32;
        const float invd = 1.f / d;
        const float pr   = e * invd;
        float o = (e32 * invd) * __half2float(big[32 * BP + 512 + h * ND + lane]);
        #pragma unroll 4
        for (int k = 0; k < 32; k++) {
            const float pk = __shfl_sync(0xffffffffu, pr, k);
            o = fmaf(pk, __half2float(big[k * BP + 512 + h * ND + lane]), o);
        }
        attnout[(size_t)w * NC + h * ND + lane] = __float2half_rn(o);
    }
    __syncthreads();

    // ---- Phase E: xs += gamma1 * (o @ proj_w + proj_b) ----
    do_gemm<2, 16, 4, 2>(hs + HP, HP, wproj, 16, wq * 4, 0, proj_b, gamma1,
                         nullptr, xs + XP, XP, wq * 32);
    __syncthreads();

    // ---- Phase F: LN2 (data rows) ----
    for (int s = 1 + wq; s < SW; s += 8) {
        const float* rp = xs + s * XP;
        float sum = 0.f, sum2 = 0.f;
        #pragma unroll
        for (int c = lane; c < NC; c += 32) { float v = rp[c]; sum += v; sum2 += v * v; }
        #pragma unroll
        for (int o = 16; o; o >>= 1) {
            sum  += __shfl_xor_sync(0xffffffffu, sum, o);
            sum2 += __shfl_xor_sync(0xffffffffu, sum2, o);
        }
        const float m    = sum * (1.f / NC);
        const float var  = fmaxf(sum2 * (1.f / NC) - m * m, 0.f);
        const float rstd = rsqrtf(var + 1e-5f);
        #pragma unroll
        for (int c = lane; c < NC; c += 32)
            hs[s * HP + c] = __float2half_rn((rp[c] - m) * rstd * ln2_g[c] + ln2_b[c]);
    }
    __syncthreads();

    // ---- Phase G: MLP single-pass, hidden fp8 [32][1040B] ----
    #pragma unroll 1
    for (int p = 0; p < 2; p++) {
        const int nt = wq * 16 + p * 8;     // 8 warps x 16 n8-tiles = 1024 cols
        do_gemm_gelu8<16, 8>(hs + HP, HP, w1p, 16, nt, b1, hid8, HDB, nt * 8);
    }
    __syncthreads();
    do_gemm8<32>(hid8, HDB, w2p8, 32, wq * 4, b2, gamma2, xs + XP, XP, wq * 32);
    __syncthreads();

    // ---- Phase H: write data rows ----
    for (int idx = tid; idx < KW * NC; idx += THREADS) {
        const int s = idx >> 8, c = idx & 255;
        out_data[((size_t)w * KW + s) * NC + c] = xs[(s + 1) * XP + c];
    }
}

// ---------------- host launch ----------------
extern "C" void kernel_launch(void* const* d_in, const int* in_sizes, int n_in,
                              void* d_out, int out_size) {
    (void)in_sizes; (void)n_in; (void)out_size;
    const float* data   = (const float*)d_in[0];
    const float* rt     = (const float*)d_in[1];
    const float* cpe_w  = (const float*)d_in[2];
    const float* cpe_b  = (const float*)d_in[3];
    const float* ln1_g  = (const float*)d_in[4];
    const float* ln1_b  = (const float*)d_in[5];
    const float* qkv_w  = (const float*)d_in[6];
    const float* qkv_b  = (const float*)d_in[7];
    const float* rpe    = (const float*)d_in[8];
    const float* proj_w = (const float*)d_in[9];
    const float* proj_b = (const float*)d_in[10];
    const float* ln2_g  = (const float*)d_in[11];
    const float* ln2_b  = (const float*)d_in[12];
    const float* w1     = (const float*)d_in[13];
    const float* b1     = (const float*)d_in[14];
    const float* w2     = (const float*)d_in[15];
    const float* b2     = (const float*)d_in[16];
    const float* gamma1 = (const float*)d_in[17];
    const float* gamma2 = (const float*)d_in[18];

    float* out_data = (float*)d_out;
    float* out_rt   = out_data + (size_t)NTOK * NC;

    cudaFuncSetAttribute(hot_block_kernel,
                         cudaFuncAttributeMaxDynamicSharedMemorySize, SMEM_BYTES);
    cudaFuncSetAttribute(pre_kernel,
                         cudaFuncAttributeMaxDynamicSharedMemorySize, PRE_SMEM);
    cudaFuncSetAttribute(post_kernel,
                         cudaFuncAttributeMaxDynamicSharedMemorySize, POST_SMEM);

    float *bd, *brt;
    cudaGetSymbolAddress((void**)&bd,  g_buf_data);
    cudaGetSymbolAddress((void**)&brt, g_buf_rt);
    uint2 *wpall, *w2p8;
    cudaGetSymbolAddress((void**)&wpall, g_wperm);
    cudaGetSymbolAddress((void**)&w2p8,  g_w2p8);
    float4* rpef;
    cudaGetSymbolAddress((void**)&rpef, g_rpef);
    __half *qkvr, *attn;
    cudaGetSymbolAddress((void**)&qkvr, g_qkv_relay);
    cudaGetSymbolAddress((void**)&attn, g_attnout);

    // 8 launches/call: [convert, marker, pre0, main0, post0, pre1, main1, post1]
    // -> ncu abs launch idx 3 = main0
    {
        int tot = 2 * WP_BLK + 2 * W2P8_BLK + 2 * RPEF_BLK;
        convert_all_kernel<<<(tot + 255) / 256, 256>>>(
            qkv_w, proj_w, w1, w2, rpe, wpall, w2p8, rpef);
    }
    marker_kernel<<<1, 32>>>();

    for (int blk = 0; blk < 2; blk++) {
        const uint2* wpb  = wpall + (size_t)blk * WP_BLK;
        const uint2* w2pb = w2p8  + (size_t)blk * W2P8_BLK;
        const float* rtin  = (blk == 0) ? rt : brt;
        const float* din   = (blk == 0) ? data : bd;
        float*       dout  = (blk == 0) ? bd : out_data;
        float*       rtout = (blk == 0) ? brt : out_rt;
        const int o1 = blk * NC, o3 = blk * 3 * NC, oh = blk * NHID;

        pre_kernel<<<128, THREADS, PRE_SMEM>>>(
            rtin, wpb + WP_QKV, ln1_g + o1, ln1_b + o1, qkv_b + o3, qkvr);

        hot_block_kernel<<<NWIN, THREADS, SMEM_BYTES>>>(
            din, wpb, w2pb, rpef + (size_t)blk * RPEF_BLK,
            rpe + (size_t)blk * NH * SW * SW, qkvr, attn,
            cpe_w + blk * 3 * NC, cpe_b + o1, ln1_g + o1, ln1_b + o1,
            qkv_b + o3, proj_b + o1, ln2_g + o1, ln2_b + o1,
            b1 + oh, b2 + o1, gamma1 + o1, gamma2 + o1, dout);

        post_kernel<<<128, THREADS, POST_SMEM>>>(
            rtin, attn, wpb + WP_PROJ, wpb + WP_W1, wpb + WP_W2,
            proj_b + o1, ln2_g + o1, ln2_b + o1, b1 + oh, b2 + o1,
            gamma1 + o1, gamma2 + o1, rtout);
    }
}

// round 14
// speedup vs baseline: 1.7042x; 1.0133x over previous
#include <cuda_runtime.h>
#include <cuda_fp16.h>
#include <cuda_fp8.h>
#include <math.h>

// ---------------- problem constants ----------------
#define NC    256
#define NH    8
#define ND    32
#define KW    32
#define SW    33
#define NWIN  8192
#define NTOK  (NWIN*KW)
#define NHID  1024
#define ATT_SCALE 0.17677669529663687f
#define THREADS 256
#define WSCALE 64.0f
#define INVWS  0.015625f

// ---------------- smem pitches ----------------
#define XP  258    // xs fp32 pitch (elements)
#define HP  264    // hs fp16 pitch (elements)
#define BP  776    // qkv fp16 pitch (elements; 33 rows, row0 = relay)
#define MP  520    // post-kernel mlp hidden fp16 pitch (elements)
#define HDB 1040   // main-kernel mlp hidden fp8 pitch (BYTES)

#define XS_BYTES   34080
#define HS_BYTES   (33*HP*2)             // 17424
#define BIG_BYTES  (33*BP*2)             // 51216
#define SMEM_BYTES (XS_BYTES + HS_BYTES + BIG_BYTES)   // 102720 -> 2 CTA/SM

#define PRE_SMEM   (64*HP*2)
#define POST_SMEM  (64*XP*4 + 64*HP*2 + 64*MP*2)

// ---------------- global scratch ----------------
__device__ float  g_buf_data[(size_t)NTOK * NC];
__device__ float  g_buf_rt[(size_t)NWIN * NC];
__device__ __half g_qkv_relay[(size_t)NWIN * 768];
__device__ __half g_attnout[(size_t)NWIN * NC];

// fp16 weight B-fragments, PAIR-kt layout [nt][kt/2][lane] (uint4 counts / block):
// uint4 = { pack(k0,k0+1), pack(k0+8,k0+9), pack(k0+16..), pack(k0+24..) } per lane
#define WP_QKV  0
#define WP_PROJ 24576
#define WP_W1   32768
#define WP_W2   65536
#define WP_BLK  98304
__device__ uint4 g_wperm[2 * WP_BLK];

// fp8 w2 B-fragments (k32), PAIR-kt layout (uint4 counts / block)
#define W2P8_BLK 16384
__device__ uint4 g_w2p8[2 * W2P8_BLK];

// rpe in mma-C-fragment layout: [blk][h][mt(2)][nt(5)][lane(32)] float4
#define RPEF_BLK 2560
__device__ float4 g_rpef[2 * RPEF_BLK];

// ---------------- helpers ----------------
__device__ __forceinline__ unsigned sm_u32(const void* p) {
    return (unsigned)__cvta_generic_to_shared(p);
}
__device__ __forceinline__ unsigned pack2h(float a, float b) {
    __half2 h = __floats2half2_rn(a, b);
    return *reinterpret_cast<unsigned*>(&h);
}
__device__ __forceinline__ unsigned char to_fp8(float x) {
    return (unsigned char)__nv_cvt_float_to_fp8(x, __NV_SATFINITE, __NV_E4M3);
}
__device__ __forceinline__ unsigned short to_fp8x2(float x, float y) {
    float2 f = make_float2(x, y);
    return (unsigned short)__nv_cvt_float2_to_fp8x2(f, __NV_SATFINITE, __NV_E4M3);
}
__device__ __forceinline__ float gelu_tanh(float x) {
    float t = 0.7978845608028654f * (x + 0.044715f * x * x * x);
    float th;
    asm("tanh.approx.f32 %0, %1;" : "=f"(th) : "f"(t));
    return 0.5f * x * (1.f + th);
}
__device__ __forceinline__ void ldmat4(unsigned a[4], unsigned addr) {
    asm volatile("ldmatrix.sync.aligned.m8n8.x4.shared.b16 {%0,%1,%2,%3}, [%4];"
                 : "=r"(a[0]), "=r"(a[1]), "=r"(a[2]), "=r"(a[3]) : "r"(addr));
}
__device__ __forceinline__ void ldmat2(unsigned& b0, unsigned& b1, unsigned addr) {
    asm volatile("ldmatrix.sync.aligned.m8n8.x2.shared.b16 {%0,%1}, [%2];"
                 : "=r"(b0), "=r"(b1) : "r"(addr));
}
__device__ __forceinline__ void ldmat2t(unsigned& b0, unsigned& b1, unsigned addr) {
    asm volatile("ldmatrix.sync.aligned.m8n8.x2.trans.shared.b16 {%0,%1}, [%2];"
                 : "=r"(b0), "=r"(b1) : "r"(addr));
}
__device__ __forceinline__ void mma_f16(float c[4], const unsigned a[4], const uint2 b) {
    asm volatile("mma.sync.aligned.m16n8k16.row.col.f32.f16.f16.f32 "
                 "{%0,%1,%2,%3},{%4,%5,%6,%7},{%8,%9},{%0,%1,%2,%3};"
                 : "+f"(c[0]), "+f"(c[1]), "+f"(c[2]), "+f"(c[3])
                 : "r"(a[0]), "r"(a[1]), "r"(a[2]), "r"(a[3]), "r"(b.x), "r"(b.y));
}
__device__ __forceinline__ void mma_fp8(float c[4], const unsigned a[4], const uint2 b) {
    asm volatile("mma.sync.aligned.m16n8k32.row.col.f32.e4m3.e4m3.f32 "
                 "{%0,%1,%2,%3},{%4,%5,%6,%7},{%8,%9},{%0,%1,%2,%3};"
                 : "+f"(c[0]), "+f"(c[1]), "+f"(c[2]), "+f"(c[3])
                 : "r"(a[0]), "r"(a[1]), "r"(a[2]), "r"(a[3]), "r"(b.x), "r"(b.y));
}

// ---------------- fused conversion kernel ----------------
__global__ void convert_all_kernel(const float* __restrict__ qkv_w,
                                   const float* __restrict__ proj_w,
                                   const float* __restrict__ w1,
                                   const float* __restrict__ w2,
                                   const float* __restrict__ rpe,
                                   uint4* __restrict__ out16,
                                   uint4* __restrict__ out8,
                                   float4* __restrict__ rpef) {
    const int N16 = 2 * WP_BLK, N8 = 2 * W2P8_BLK, NRF = 2 * RPEF_BLK;
    int idx = blockIdx.x * blockDim.x + threadIdx.x;
    if (idx < N16) {
        const int blk = idx / WP_BLK;
        int r = idx - blk * WP_BLK;
        const float* W; int K, N; int local;
        if (r < WP_PROJ)      { W = qkv_w  + (size_t)blk * 256 * 768;  K = 256;  N = 768;  local = r; }
        else if (r < WP_W1)   { W = proj_w + (size_t)blk * 256 * 256;  K = 256;  N = 256;  local = r - WP_PROJ; }
        else if (r < WP_W2)   { W = w1     + (size_t)blk * 256 * 1024; K = 256;  N = 1024; local = r - WP_W1; }
        else                  { W = w2     + (size_t)blk * 1024 * 256; K = 1024; N = 256;  local = r - WP_W2; }
        const int lane = local & 31;
        const int t    = local >> 5;
        const int KT2  = K / 32;
        const int ktp  = t % KT2, nt = t / KT2;
        const int n    = nt * 8 + (lane >> 2);
        const int kA   = (2 * ktp) * 16 + (lane & 3) * 2;   // even k16 step
        const int kB   = kA + 16;                            // odd  k16 step
        uint4 v;
        v.x = pack2h(W[(size_t)kA * N + n],       W[(size_t)(kA + 1) * N + n]);
        v.y = pack2h(W[(size_t)(kA + 8) * N + n], W[(size_t)(kA + 9) * N + n]);
        v.z = pack2h(W[(size_t)kB * N + n],       W[(size_t)(kB + 1) * N + n]);
        v.w = pack2h(W[(size_t)(kB + 8) * N + n], W[(size_t)(kB + 9) * N + n]);
        out16[idx] = v;
    } else if (idx < N16 + N8) {
        int j = idx - N16;
        const int blk = j / W2P8_BLK;
        int local = j - blk * W2P8_BLK;
        const float* W = w2 + (size_t)blk * 1024 * 256;   // K=1024, N=256
        const int lane = local & 31;
        const int t    = local >> 5;
        const int KT2  = 16;                               // 1024 / 64
        const int ktp  = t % KT2, nt = t / KT2;
        const int n    = nt * 8 + (lane >> 2);
        uint4 v; unsigned* vv = (unsigned*)&v;
        #pragma unroll
        for (int half = 0; half < 2; half++) {             // two k32 steps
            const int k0 = (2 * ktp + half) * 32 + (lane & 3) * 4;
            unsigned lo = 0, hi = 0;
            #pragma unroll
            for (int i = 0; i < 4; i++) {
                lo |= (unsigned)to_fp8(W[(size_t)(k0 + i)      * 256 + n] * WSCALE) << (8 * i);
                hi |= (unsigned)to_fp8(W[(size_t)(k0 + 16 + i) * 256 + n] * WSCALE) << (8 * i);
            }
            vv[2 * half] = lo; vv[2 * half + 1] = hi;
        }
        out8[j] = v;
    } else if (idx < N16 + N8 + NRF) {
        int j = idx - N16 - N8;
        const int blk  = j / RPEF_BLK;
        int rem  = j - blk * RPEF_BLK;            // [h][mt][nt][lane]
        const int h    = rem / 320;
        rem  = rem - h * 320;
        const int mt   = rem / 160;
        const int nt   = (rem % 160) / 32;
        const int lane = rem & 31;
        const int rr   = lane >> 2, cq = (lane & 3) * 2;
        const int q0   = mt * 16 + rr + 1, q1 = q0 + 8;   // data queries (ref q)
        const int k0   = nt * 8 + cq,      k1 = k0 + 1;   // keys (ref k)
        const float* rh = rpe + ((size_t)blk * NH + h) * SW * SW;
        float4 v;
        v.x = (k0 <= 32) ? rh[q0 * SW + k0] : 0.f;
        v.y = (k1 <= 32) ? rh[q0 * SW + k1] : 0.f;
        v.z = (k0 <= 32) ? rh[q1 * SW + k0] : 0.f;
        v.w = (k1 <= 32) ? rh[q1 * SW + k1] : 0.f;
        rpef[j] = v;
    }
}

// one marker so ncu's profiled launch (abs idx 3) = main kernel block 0
__global__ void marker_kernel() {}

// ---------------- fp16 k-outer GEMM, pair-kt uint4 B loads ----------------
// KSTEPS = number of k16 steps (even). KT2tot = total k-pairs for this matrix.
template<int MODE, int KSTEPS, int NT, int MT>
__device__ __forceinline__ void do_gemm(
    const __half* __restrict__ Ash, int apitch,
    const uint4* __restrict__ wmat, int KT2tot, int nt0, int ktp0,
    const float* __restrict__ bias, const float* __restrict__ gvec,
    __half* __restrict__ outh, float* __restrict__ outf,
    int opitch, int ocol0)
{
    const int lane = threadIdx.x & 31;
    float acc[MT][NT][4];
    #pragma unroll
    for (int mt = 0; mt < MT; mt++)
        #pragma unroll
        for (int j = 0; j < NT; j++)
            #pragma unroll
            for (int e = 0; e < 4; e++) acc[mt][j][e] = 0.f;

    unsigned abase[MT];
    #pragma unroll
    for (int mt = 0; mt < MT; mt++) {
        int row = mt * 16 + (lane & 15);
        abase[mt] = sm_u32(Ash + row * apitch + ((lane >> 4) << 3));
    }
    const uint4* wb = wmat + ((size_t)nt0 * KT2tot + ktp0) * 32 + lane;

    #pragma unroll 2
    for (int ktp = 0; ktp < KSTEPS / 2; ktp++) {
        uint4 bb[NT];
        #pragma unroll
        for (int j = 0; j < NT; j++) bb[j] = __ldg(wb + ((size_t)j * KT2tot + ktp) * 32);
        unsigned a[MT][4];
        #pragma unroll
        for (int mt = 0; mt < MT; mt++) ldmat4(a[mt], abase[mt] + (unsigned)(ktp * 64));
        #pragma unroll
        for (int mt = 0; mt < MT; mt++)
            #pragma unroll
            for (int j = 0; j < NT; j++) mma_f16(acc[mt][j], a[mt], make_uint2(bb[j].x, bb[j].y));
        #pragma unroll
        for (int mt = 0; mt < MT; mt++) ldmat4(a[mt], abase[mt] + (unsigned)(ktp * 64 + 32));
        #pragma unroll
        for (int mt = 0; mt < MT; mt++)
            #pragma unroll
            for (int j = 0; j < NT; j++) mma_f16(acc[mt][j], a[mt], make_uint2(bb[j].z, bb[j].w));
    }

    const int cq = (lane & 3) * 2;
    const int rr = lane >> 2;
    #pragma unroll
    for (int j = 0; j < NT; j++) {
        const int mcol = (nt0 + j) * 8 + cq;
        const int ocol = ocol0 + j * 8 + cq;
        float b0s = 0.f, b1s = 0.f;
        if (bias) { b0s = bias[mcol]; b1s = bias[mcol + 1]; }
        float g0 = 0.f, g1 = 0.f;
        if (MODE == 2) { g0 = gvec[ocol]; g1 = gvec[ocol + 1]; }
        #pragma unroll
        for (int mt = 0; mt < MT; mt++) {
            const int r0 = mt * 16 + rr, r1 = r0 + 8;
            const float* a4 = acc[mt][j];
            const float v00 = a4[0] + b0s, v01 = a4[1] + b1s;
            const float v10 = a4[2] + b0s, v11 = a4[3] + b1s;
            if (MODE == 0) {
                *(unsigned*)(outh + r0 * opitch + ocol) = pack2h(v00, v01);
                *(unsigned*)(outh + r1 * opitch + ocol) = pack2h(v10, v11);
            } else if (MODE == 1) {
                *(unsigned*)(outh + r0 * opitch + ocol) = pack2h(gelu_tanh(v00), gelu_tanh(v01));
                *(unsigned*)(outh + r1 * opitch + ocol) = pack2h(gelu_tanh(v10), gelu_tanh(v11));
            } else {
                float* p0 = outf + r0 * opitch + ocol;
                p0[0] += g0 * v00; p0[1] += g1 * v01;
                float* p1 = outf + r1 * opitch + ocol;
                p1[0] += g0 * v10; p1[1] += g1 * v11;
            }
        }
    }
}

// ---------------- w1 GEMM: fp16 mma, gelu -> fp8 packed (MT=2) ----------------
template<int KSTEPS, int NT>
__device__ __forceinline__ void do_gemm_gelu8(
    const __half* __restrict__ Ash, int apitch,
    const uint4* __restrict__ wmat, int KT2tot, int nt0,
    const float* __restrict__ bias,
    unsigned char* __restrict__ out8, int opitchB, int ocol0)
{
    const int lane = threadIdx.x & 31;
    float acc[2][NT][4];
    #pragma unroll
    for (int mt = 0; mt < 2; mt++)
        #pragma unroll
        for (int j = 0; j < NT; j++)
            #pragma unroll
            for (int e = 0; e < 4; e++) acc[mt][j][e] = 0.f;

    unsigned abase[2];
    #pragma unroll
    for (int mt = 0; mt < 2; mt++) {
        int row = mt * 16 + (lane & 15);
        abase[mt] = sm_u32(Ash + row * apitch + ((lane >> 4) << 3));
    }
    const uint4* wb = wmat + (size_t)nt0 * KT2tot * 32 + lane;

    #pragma unroll 2
    for (int ktp = 0; ktp < KSTEPS / 2; ktp++) {
        uint4 bb[NT];
        #pragma unroll
        for (int j = 0; j < NT; j++) bb[j] = __ldg(wb + ((size_t)j * KT2tot + ktp) * 32);
        unsigned a[2][4];
        #pragma unroll
        for (int mt = 0; mt < 2; mt++) ldmat4(a[mt], abase[mt] + (unsigned)(ktp * 64));
        #pragma unroll
        for (int mt = 0; mt < 2; mt++)
            #pragma unroll
            for (int j = 0; j < NT; j++) mma_f16(acc[mt][j], a[mt], make_uint2(bb[j].x, bb[j].y));
        #pragma unroll
        for (int mt = 0; mt < 2; mt++) ldmat4(a[mt], abase[mt] + (unsigned)(ktp * 64 + 32));
        #pragma unroll
        for (int mt = 0; mt < 2; mt++)
            #pragma unroll
            for (int j = 0; j < NT; j++) mma_f16(acc[mt][j], a[mt], make_uint2(bb[j].z, bb[j].w));
    }

    const int cq = (lane & 3) * 2;
    const int rr = lane >> 2;
    #pragma unroll
    for (int j = 0; j < NT; j++) {
        const int mcol = (nt0 + j) * 8 + cq;
        const int ocol = ocol0 + j * 8 + cq;
        const float b0s = bias[mcol], b1s = bias[mcol + 1];
        #pragma unroll
        for (int mt = 0; mt < 2; mt++) {
            const int r0 = mt * 16 + rr, r1 = r0 + 8;
            const float* a4 = acc[mt][j];
            *(unsigned short*)(out8 + r0 * opitchB + ocol) =
                to_fp8x2(gelu_tanh(a4[0] + b0s), gelu_tanh(a4[1] + b1s));
            *(unsigned short*)(out8 + r1 * opitchB + ocol) =
                to_fp8x2(gelu_tanh(a4[2] + b0s), gelu_tanh(a4[3] + b1s));
        }
    }
}

// ---------------- w2 GEMM: fp8 x fp8 (k32 steps, paired), residual epilogue ----------------
// KSTEPS = number of k32 steps (even). KT2tot = total k32-pairs (16 for K=1024).
template<int KSTEPS>
__device__ __forceinline__ void do_gemm8(
    const unsigned char* __restrict__ Ash, int apitchB,
    const uint4* __restrict__ wmat, int KT2tot, int nt0,
    const float* __restrict__ bias, const float* __restrict__ gvec,
    float* __restrict__ outf, int opitch, int ocol0)
{
    const int lane = threadIdx.x & 31;
    float acc[2][4][4];
    #pragma unroll
    for (int mt = 0; mt < 2; mt++)
        #pragma unroll
        for (int j = 0; j < 4; j++)
            #pragma unroll
            for (int e = 0; e < 4; e++) acc[mt][j][e] = 0.f;

    unsigned abase[2];
    #pragma unroll
    for (int mt = 0; mt < 2; mt++) {
        int row = mt * 16 + (lane & 15);
        abase[mt] = sm_u32(Ash + row * apitchB + ((lane >> 4) << 4));
    }
    const uint4* wb = wmat + (size_t)nt0 * KT2tot * 32 + lane;

    #pragma unroll 2
    for (int ktp = 0; ktp < KSTEPS / 2; ktp++) {
        uint4 bb[4];
        #pragma unroll
        for (int j = 0; j < 4; j++) bb[j] = __ldg(wb + ((size_t)j * KT2tot + ktp) * 32);
        unsigned a[2][4];
        #pragma unroll
        for (int mt = 0; mt < 2; mt++) ldmat4(a[mt], abase[mt] + (unsigned)(ktp * 64));
        #pragma unroll
        for (int mt = 0; mt < 2; mt++)
            #pragma unroll
            for (int j = 0; j < 4; j++) mma_fp8(acc[mt][j], a[mt], make_uint2(bb[j].x, bb[j].y));
        #pragma unroll
        for (int mt = 0; mt < 2; mt++) ldmat4(a[mt], abase[mt] + (unsigned)(ktp * 64 + 32));
        #pragma unroll
        for (int mt = 0; mt < 2; mt++)
            #pragma unroll
            for (int j = 0; j < 4; j++) mma_fp8(acc[mt][j], a[mt], make_uint2(bb[j].z, bb[j].w));
    }

    const int cq = (lane & 3) * 2;
    const int rr = lane >> 2;
    #pragma unroll
    for (int j = 0; j < 4; j++) {
        const int mcol = (nt0 + j) * 8 + cq;
        const int ocol = ocol0 + j * 8 + cq;
        const float b0s = bias[mcol], b1s = bias[mcol + 1];
        const float g0 = gvec[ocol], g1 = gvec[ocol + 1];
        #pragma unroll
        for (int mt = 0; mt < 2; mt++) {
            const int r0 = mt * 16 + rr, r1 = r0 + 8;
            const float* a4 = acc[mt][j];
            float* p0 = outf + r0 * opitch + ocol;
            p0[0] += g0 * fmaf(a4[0], INVWS, b0s);
            p0[1] += g1 * fmaf(a4[1], INVWS, b1s);
            float* p1 = outf + r1 * opitch + ocol;
            p1[0] += g0 * fmaf(a4[2], INVWS, b0s);
            p1[1] += g1 * fmaf(a4[3], INVWS, b1s);
        }
    }
}

// hfma2 dot: 16 half2 pairs -> fp32 scalar (relay path)
__device__ __forceinline__ float dot32_h2(const __half2* a, const __half2* b) {
    __half2 acc0 = __hmul2(a[0], b[0]);
    __half2 acc1 = __hmul2(a[1], b[1]);
    #pragma unroll
    for (int i = 2; i < 16; i += 2) {
        acc0 = __hfma2(a[i],     b[i],     acc0);
        acc1 = __hfma2(a[i + 1], b[i + 1], acc1);
    }
    __half2 acc = __hadd2(acc0, acc1);
    return __half2float(__low2half(acc)) + __half2float(__high2half(acc));
}

// LN rows helper for 64-row pre/post tiles
__device__ __forceinline__ void ln_rows64(
    const float* __restrict__ X, int xpitch, __half* __restrict__ Out,
    const float* __restrict__ g, const float* __restrict__ b)
{
    const int wq = threadIdx.x >> 5, lane = threadIdx.x & 31;
    for (int row = wq; row < 64; row += 8) {
        const float* rp = X + row * xpitch;
        float sum = 0.f, sum2 = 0.f;
        #pragma unroll
        for (int c = lane; c < NC; c += 32) { float v = rp[c]; sum += v; sum2 += v * v; }
        #pragma unroll
        for (int o = 16; o; o >>= 1) {
            sum  += __shfl_xor_sync(0xffffffffu, sum, o);
            sum2 += __shfl_xor_sync(0xffffffffu, sum2, o);
        }
        const float m    = sum * (1.f / NC);
        const float var  = fmaxf(sum2 * (1.f / NC) - m * m, 0.f);
        const float rstd = rsqrtf(var + 1e-5f);
        #pragma unroll
        for (int c = lane; c < NC; c += 32)
            Out[row * HP + c] = __float2half_rn((rp[c] - m) * rstd * g[c] + b[c]);
    }
}

// ---------------- pre kernel: relay LN1 + qkv (block 0 only) ----------------
__global__ void __launch_bounds__(THREADS, 1)
pre_kernel(const float* __restrict__ rt_in, const uint4* __restrict__ wqkv,
           const float* __restrict__ ln1_g, const float* __restrict__ ln1_b,
           const float* __restrict__ qkv_b, __half* __restrict__ qkv_relay)
{
    extern __shared__ char sm8[];
    __half* hs = (__half*)sm8;
    const int tid = threadIdx.x, wq = tid >> 5, lane = tid & 31;
    const int r0 = blockIdx.x * 64;

    for (int row = wq; row < 64; row += 8) {
        const float* rp = rt_in + (size_t)(r0 + row) * NC;
        float v[8], sum = 0.f, sum2 = 0.f;
        #pragma unroll
        for (int i = 0; i < 8; i++) {
            v[i] = rp[lane + 32 * i];
            sum += v[i]; sum2 += v[i] * v[i];
        }
        #pragma unroll
        for (int o = 16; o; o >>= 1) {
            sum  += __shfl_xor_sync(0xffffffffu, sum, o);
            sum2 += __shfl_xor_sync(0xffffffffu, sum2, o);
        }
        const float m    = sum * (1.f / NC);
        const float var  = fmaxf(sum2 * (1.f / NC) - m * m, 0.f);
        const float rstd = rsqrtf(var + 1e-5f);
        #pragma unroll
        for (int i = 0; i < 8; i++) {
            const int c = lane + 32 * i;
            hs[row * HP + c] = __float2half_rn((v[i] - m) * rstd * ln1_g[c] + ln1_b[c]);
        }
    }
    __syncthreads();

    __half* outg = qkv_relay + (size_t)r0 * 768;
    #pragma unroll 1
    for (int p = 0; p < 2; p++) {
        const int nt = wq * 12 + p * 6;
        do_gemm<0, 16, 6, 4>(hs, HP, wqkv, 8, nt, 0, qkv_b, nullptr,
                             outg, nullptr, 768, nt * 8);
    }
}

// ---------------- post kernel: relay proj+LN2+MLP (+ fused next-block pre) ----------------
__global__ void __launch_bounds__(THREADS, 1)
post_kernel(const float* __restrict__ rt_in, const __half* __restrict__ attnout,
            const uint4* __restrict__ wproj, const uint4* __restrict__ w1p,
            const uint4* __restrict__ w2p,
            const float* __restrict__ proj_b,
            const float* __restrict__ ln2_g, const float* __restrict__ ln2_b,
            const float* __restrict__ b1,   const float* __restrict__ b2,
            const float* __restrict__ gamma1, const float* __restrict__ gamma2,
            float* __restrict__ out_rt,
            // fused pre of NEXT block (null wqkv_n => skip)
            const uint4* __restrict__ wqkv_n,
            const float* __restrict__ ln1_g_n, const float* __restrict__ ln1_b_n,
            const float* __restrict__ qkv_b_n, __half* __restrict__ qkv_relay_n)
{
    extern __shared__ char sm8[];
    float*  xs  = (float*)sm8;
    __half* hs  = (__half*)(sm8 + 64 * XP * 4);
    __half* hid = (__half*)(sm8 + 64 * XP * 4 + 64 * HP * 2);
    const int tid = threadIdx.x, wq = tid >> 5, lane = tid & 31;
    const int r0 = blockIdx.x * 64;

    for (int idx = tid; idx < 64 * NC; idx += THREADS) {
        const int row = idx >> 8, c = idx & 255;
        xs[row * XP + c] = rt_in[(size_t)(r0 + row) * NC + c];
        hs[row * HP + c] = attnout[(size_t)(r0 + row) * NC + c];
    }
    __syncthreads();

    do_gemm<2, 16, 4, 4>(hs, HP, wproj, 8, wq * 4, 0, proj_b, gamma1,
                         nullptr, xs, XP, wq * 32);
    __syncthreads();

    ln_rows64(xs, XP, hs, ln2_g, ln2_b);
    __syncthreads();

    #pragma unroll 1
    for (int c = 0; c < 2; c++) {
        #pragma unroll 1
        for (int p = 0; p < 2; p++) {
            const int nt = c * 64 + wq * 8 + p * 4;
            do_gemm<1, 16, 4, 4>(hs, HP, w1p, 8, nt, 0, b1, nullptr,
                                 hid, nullptr, MP, nt * 8 - c * 512);
        }
        __syncthreads();
        do_gemm<2, 32, 4, 4>(hid, MP, w2p, 32, wq * 4, c * 16,
                             (c == 0) ? b2 : nullptr, gamma2, nullptr, xs, XP, wq * 32);
        __syncthreads();
    }

    for (int idx = tid; idx < 64 * NC; idx += THREADS) {
        const int row = idx >> 8, c = idx & 255;
        out_rt[(size_t)(r0 + row) * NC + c] = xs[row * XP + c];
    }

    // ---- fused pre of next block: LN1(new rt) + qkv ----
    if (wqkv_n) {
        __syncthreads();
        ln_rows64(xs, XP, hs, ln1_g_n, ln1_b_n);
        __syncthreads();
        __half* outg = qkv_relay_n + (size_t)r0 * 768;
        #pragma unroll 1
        for (int p = 0; p < 2; p++) {
            const int nt = wq * 12 + p * 6;
            do_gemm<0, 16, 6, 4>(hs, HP, wqkv_n, 8, nt, 0, qkv_b_n, nullptr,
                                 outg, nullptr, 768, nt * 8);
        }
    }
}

// ---------------- main fused window kernel (32 data rows, 2 CTAs / SM) ----------------
__global__ void __launch_bounds__(THREADS, 2)
hot_block_kernel(
    const float* __restrict__ in_data,
    const uint4* __restrict__ wp,     const uint4* __restrict__ w2p8,
    const float4* __restrict__ rpef,  const float* __restrict__ rpe0,
    const __half* __restrict__ qkv_relay, __half* __restrict__ attnout,
    const float* __restrict__ cpe_w,  const float* __restrict__ cpe_b,
    const float* __restrict__ ln1_g,  const float* __restrict__ ln1_b,
    const float* __restrict__ qkv_b,
    const float* __restrict__ proj_b,
    const float* __restrict__ ln2_g,  const float* __restrict__ ln2_b,
    const float* __restrict__ b1,     const float* __restrict__ b2,
    const float* __restrict__ gamma1, const float* __restrict__ gamma2,
    float* __restrict__ out_data)
{
    extern __shared__ char sm8[];
    float*  xs  = (float*)sm8;                          // [33][258] (row0 unused)
    __half* hs  = (__half*)(sm8 + XS_BYTES);            // [33][264] (row0 unused)
    __half* big = (__half*)(sm8 + XS_BYTES + HS_BYTES); // [33][776] qkv
    unsigned char* hid8 = (unsigned char*)big;          // fp8 hidden [32][1040B] overlays

    const int tid  = threadIdx.x;
    const int wq   = tid >> 5;
    const int lane = tid & 31;
    const int w    = blockIdx.x;

    const uint4* wqkv  = wp + WP_QKV;
    const uint4* wproj = wp + WP_PROJ;
    const uint4* w1p   = wp + WP_W1;

    // ---- Phase A: cpe + LN1 fused (data rows) + relay qkv row0 load ----
    for (int s = 1 + wq; s < SW; s += 8) {
        const long r = (long)w * KW + (s - 1);
        const float* row0 = in_data + r * NC;
        const float* rowm = (r > 0)        ? row0 - NC : nullptr;
        const float* rowp = (r < NTOK - 1) ? row0 + NC : nullptr;
        float v[8], sum = 0.f, sum2 = 0.f;
        #pragma unroll
        for (int i = 0; i < 8; i++) {
            const int c = lane + 32 * i;
            const float x0 = row0[c];
            const float xm = rowm ? rowm[c] : 0.f;
            const float xp = rowp ? rowp[c] : 0.f;
            v[i] = x0 + xm * cpe_w[c] + x0 * cpe_w[NC + c] + xp * cpe_w[2 * NC + c] + cpe_b[c];
            sum += v[i]; sum2 += v[i] * v[i];
        }
        #pragma unroll
        for (int o = 16; o; o >>= 1) {
            sum  += __shfl_xor_sync(0xffffffffu, sum, o);
            sum2 += __shfl_xor_sync(0xffffffffu, sum2, o);
        }
        const float m    = sum * (1.f / NC);
        const float var  = fmaxf(sum2 * (1.f / NC) - m * m, 0.f);
        const float rstd = rsqrtf(var + 1e-5f);
        #pragma unroll
        for (int i = 0; i < 8; i++) {
            const int c = lane + 32 * i;
            xs[s * XP + c] = v[i];
            hs[s * HP + c] = __float2half_rn((v[i] - m) * rstd * ln1_g[c] + ln1_b[c]);
        }
    }
    {   // relay qkv -> big row 0
        const unsigned* src = (const unsigned*)(qkv_relay + (size_t)w * 768);
        unsigned* dst = (unsigned*)big;
        for (int idx = tid; idx < 384; idx += THREADS) dst[idx] = src[idx];
    }
    __syncthreads();

    // ---- Phase C: qkv (data rows) -> big rows 1..32 ----
    #pragma unroll 1
    for (int p = 0; p < 2; p++) {
        const int nt = wq * 12 + p * 6;
        do_gemm<0, 16, 6, 2>(hs + HP, HP, wqkv, 8, nt, 0, qkv_b, nullptr,
                             big + BP, nullptr, BP, nt * 8);
    }
    __syncthreads();

    // ---- Phase D: attention via tensor cores (warp = head) ----
    {
        const int h  = wq;
        const int rr = lane >> 2, cq = (lane & 3) * 2;
        const int L  = lane & 15;

        // K B-fragments: K stored [key][d] == B [n][k] pattern -> plain ldmatrix
        uint2 bk[5][2];
        #pragma unroll
        for (int nt = 0; nt < 5; nt++) {
            int key = nt * 8 + (L & 7); if (key > 32) key = 32;
            #pragma unroll
            for (int kt = 0; kt < 2; kt++)
                ldmat2(bk[nt][kt].x, bk[nt][kt].y,
                       sm_u32(big + key * BP + 256 + h * ND + kt * 16 + ((L >> 3) << 3)));
        }

        // QK^T
        float accS[2][5][4];
        #pragma unroll
        for (int mt = 0; mt < 2; mt++)
            #pragma unroll
            for (int nt = 0; nt < 5; nt++)
                #pragma unroll
                for (int e = 0; e < 4; e++) accS[mt][nt][e] = 0.f;
        #pragma unroll
        for (int mt = 0; mt < 2; mt++) {
            #pragma unroll
            for (int kt = 0; kt < 2; kt++) {
                unsigned aq[4];
                ldmat4(aq, sm_u32(big + (1 + mt * 16 + L) * BP + h * ND
                                  + ((lane >> 4) << 3) + kt * 16));
                #pragma unroll
                for (int nt = 0; nt < 5; nt++) mma_f16(accS[mt][nt], aq, bk[nt][kt]);
            }
        }

        // exp + row sums + pack P as PV A-fragments (normalization deferred)
        const float4* rpef_h = rpef + h * 320;
        float sum0[2], sum1[2];
        unsigned ap[2][3][4];
        #pragma unroll
        for (int mt = 0; mt < 2; mt++) {
            float p[5][4];
            float s0 = 0.f, s1 = 0.f;
            #pragma unroll
            for (int nt = 0; nt < 5; nt++) {
                const float4 rv = rpef_h[(mt * 5 + nt) * 32 + lane];
                float e0 = __expf(fmaf(accS[mt][nt][0], ATT_SCALE, rv.x));
                float e1 = __expf(fmaf(accS[mt][nt][1], ATT_SCALE, rv.y));
                float e2 = __expf(fmaf(accS[mt][nt][2], ATT_SCALE, rv.z));
                float e3 = __expf(fmaf(accS[mt][nt][3], ATT_SCALE, rv.w));
                if (nt == 4) {                       // keys 32..39: only key 32 valid
                    const bool vld = (cq == 0);
                    e0 = vld ? e0 : 0.f; e2 = vld ? e2 : 0.f;
                    e1 = 0.f; e3 = 0.f;
                }
                p[nt][0] = e0; p[nt][1] = e1; p[nt][2] = e2; p[nt][3] = e3;
                s0 += e0 + e1; s1 += e2 + e3;
            }
            s0 += __shfl_xor_sync(0xffffffffu, s0, 1);
            s0 += __shfl_xor_sync(0xffffffffu, s0, 2);
            s1 += __shfl_xor_sync(0xffffffffu, s1, 1);
            s1 += __shfl_xor_sync(0xffffffffu, s1, 2);
            sum0[mt] = s0; sum1[mt] = s1;
            #pragma unroll
            for (int s = 0; s < 3; s++) {
                const int n0 = 2 * s, n1 = 2 * s + 1;
                ap[mt][s][0] = pack2h(p[n0][0], p[n0][1]);
                ap[mt][s][1] = pack2h(p[n0][2], p[n0][3]);
                ap[mt][s][2] = (n1 < 5) ? pack2h(p[n1][0], p[n1][1]) : 0u;
                ap[mt][s][3] = (n1 < 5) ? pack2h(p[n1][2], p[n1][3]) : 0u;
            }
        }

        // PV: V [key][d] -> B via ldmatrix.trans
        float accO[2][4][4];
        #pragma unroll
        for (int mt = 0; mt < 2; mt++)
            #pragma unroll
            for (int nt = 0; nt < 4; nt++)
                #pragma unroll
                for (int e = 0; e < 4; e++) accO[mt][nt][e] = 0.f;
        #pragma unroll
        for (int kt = 0; kt < 3; kt++) {
            int key = kt * 16 + L; if (key > 32) key = 32;
            uint2 bv[4];
            #pragma unroll
            for (int nt = 0; nt < 4; nt++)
                ldmat2t(bv[nt].x, bv[nt].y,
                        sm_u32(big + key * BP + 512 + h * ND + nt * 8));
            #pragma unroll
            for (int mt = 0; mt < 2; mt++)
                #pragma unroll
                for (int nt = 0; nt < 4; nt++) mma_f16(accO[mt][nt], ap[mt][kt], bv[nt]);
        }

        // normalize + store to hs rows 1..32 (proj A-operand)
        #pragma unroll
        for (int mt = 0; mt < 2; mt++) {
            const float i0 = 1.f / sum0[mt], i1 = 1.f / sum1[mt];
            #pragma unroll
            for (int nt = 0; nt < 4; nt++) {
                const int d = nt * 8 + cq;
                *(unsigned*)(hs + (1 + mt * 16 + rr) * HP + h * ND + d) =
                    pack2h(accO[mt][nt][0] * i0, accO[mt][nt][1] * i0);
                *(unsigned*)(hs + (9 + mt * 16 + rr) * HP + h * ND + d) =
                    pack2h(accO[mt][nt][2] * i1, accO[mt][nt][3] * i1);
            }
        }

        // relay query (ref q = 0): scalar path
        const float* rp0 = rpe0 + h * SW * SW;
        __half2 q0h[16], kh[16];
        {
            const uint4* qp = (const uint4*)(big + h * ND);
            #pragma unroll
            for (int i = 0; i < 4; i++) ((uint4*)q0h)[i] = qp[i];
        }
        {
            const uint4* kp = (const uint4*)(big + lane * BP + 256 + h * ND);
            #pragma unroll
            for (int i = 0; i < 4; i++) ((uint4*)kh)[i] = kp[i];
        }
        float e = __expf(fmaf(dot32_h2(q0h, kh), ATT_SCALE, rp0[lane]));
        {
            const uint4* kp = (const uint4*)(big + 32 * BP + 256 + h * ND);
            #pragma unroll
            for (int i = 0; i < 4; i++) ((uint4*)kh)[i] = kp[i];
        }
        const float e32 = __expf(fmaf(dot32_h2(q0h, kh), ATT_SCALE, rp0[32]));
        float d = e;
        #pragma unroll
        for (int o = 16; o; o >>= 1) d += __shfl_xor_sync(0xffffffffu, d, o);
        d += e32;
        const float invd = 1.f / d;
        const float pr   = e * invd;
        float o = (e32 * invd) * __half2float(big[32 * BP + 512 + h * ND + lane]);
        #pragma unroll 4
        for (int k = 0; k < 32; k++) {
            const float pk = __shfl_sync(0xffffffffu, pr, k);
            o = fmaf(pk, __half2float(big[k * BP + 512 + h * ND + lane]), o);
        }
        attnout[(size_t)w * NC + h * ND + lane] = __float2half_rn(o);
    }
    __syncthreads();

    // ---- Phase E: xs += gamma1 * (o @ proj_w + proj_b) ----
    do_gemm<2, 16, 4, 2>(hs + HP, HP, wproj, 8, wq * 4, 0, proj_b, gamma1,
                         nullptr, xs + XP, XP, wq * 32);
    __syncthreads();

    // ---- Phase F: LN2 (data rows) ----
    for (int s = 1 + wq; s < SW; s += 8) {
        const float* rp = xs + s * XP;
        float sum = 0.f, sum2 = 0.f;
        #pragma unroll
        for (int c = lane; c < NC; c += 32) { float v = rp[c]; sum += v; sum2 += v * v; }
        #pragma unroll
        for (int o = 16; o; o >>= 1) {
            sum  += __shfl_xor_sync(0xffffffffu, sum, o);
            sum2 += __shfl_xor_sync(0xffffffffu, sum2, o);
        }
        const float m    = sum * (1.f / NC);
        const float var  = fmaxf(sum2 * (1.f / NC) - m * m, 0.f);
        const float rstd = rsqrtf(var + 1e-5f);
        #pragma unroll
        for (int c = lane; c < NC; c += 32)
            hs[s * HP + c] = __float2half_rn((rp[c] - m) * rstd * ln2_g[c] + ln2_b[c]);
    }
    __syncthreads();

    // ---- Phase G: MLP single-pass, hidden fp8 [32][1040B] ----
    #pragma unroll 1
    for (int p = 0; p < 2; p++) {
        const int nt = wq * 16 + p * 8;     // 8 warps x 16 n8-tiles = 1024 cols
        do_gemm_gelu8<16, 8>(hs + HP, HP, w1p, 8, nt, b1, hid8, HDB, nt * 8);
    }
    __syncthreads();
    do_gemm8<32>(hid8, HDB, w2p8, 16, wq * 4, b2, gamma2, xs + XP, XP, wq * 32);
    __syncthreads();

    // ---- Phase H: write data rows ----
    for (int idx = tid; idx < KW * NC; idx += THREADS) {
        const int s = idx >> 8, c = idx & 255;
        out_data[((size_t)w * KW + s) * NC + c] = xs[(s + 1) * XP + c];
    }
}

// ---------------- host launch ----------------
extern "C" void kernel_launch(void* const* d_in, const int* in_sizes, int n_in,
                              void* d_out, int out_size) {
    (void)in_sizes; (void)n_in; (void)out_size;
    const float* data   = (const float*)d_in[0];
    const float* rt     = (const float*)d_in[1];
    const float* cpe_w  = (const float*)d_in[2];
    const float* cpe_b  = (const float*)d_in[3];
    const float* ln1_g  = (const float*)d_in[4];
    const float* ln1_b  = (const float*)d_in[5];
    const float* qkv_w  = (const float*)d_in[6];
    const float* qkv_b  = (const float*)d_in[7];
    const float* rpe    = (const float*)d_in[8];
    const float* proj_w = (const float*)d_in[9];
    const float* proj_b = (const float*)d_in[10];
    const float* ln2_g  = (const float*)d_in[11];
    const float* ln2_b  = (const float*)d_in[12];
    const float* w1     = (const float*)d_in[13];
    const float* b1     = (const float*)d_in[14];
    const float* w2     = (const float*)d_in[15];
    const float* b2     = (const float*)d_in[16];
    const float* gamma1 = (const float*)d_in[17];
    const float* gamma2 = (const float*)d_in[18];

    float* out_data = (float*)d_out;
    float* out_rt   = out_data + (size_t)NTOK * NC;

    cudaFuncSetAttribute(hot_block_kernel,
                         cudaFuncAttributeMaxDynamicSharedMemorySize, SMEM_BYTES);
    cudaFuncSetAttribute(pre_kernel,
                         cudaFuncAttributeMaxDynamicSharedMemorySize, PRE_SMEM);
    cudaFuncSetAttribute(post_kernel,
                         cudaFuncAttributeMaxDynamicSharedMemorySize, POST_SMEM);

    float *bd, *brt;
    cudaGetSymbolAddress((void**)&bd,  g_buf_data);
    cudaGetSymbolAddress((void**)&brt, g_buf_rt);
    uint4 *wpall, *w2p8;
    cudaGetSymbolAddress((void**)&wpall, g_wperm);
    cudaGetSymbolAddress((void**)&w2p8,  g_w2p8);
    float4* rpef;
    cudaGetSymbolAddress((void**)&rpef, g_rpef);
    __half *qkvr, *attn;
    cudaGetSymbolAddress((void**)&qkvr, g_qkv_relay);
    cudaGetSymbolAddress((void**)&attn, g_attnout);

    // 7 launches/call: [convert, marker, pre0, main0, post0(+pre1), main1, post1]
    // -> ncu abs launch idx 3 = main0
    {
        int tot = 2 * WP_BLK + 2 * W2P8_BLK + 2 * RPEF_BLK;
        convert_all_kernel<<<(tot + 255) / 256, 256>>>(
            qkv_w, proj_w, w1, w2, rpe, wpall, w2p8, rpef);
    }
    marker_kernel<<<1, 32>>>();

    pre_kernel<<<128, THREADS, PRE_SMEM>>>(
        rt, wpall + WP_QKV, ln1_g, ln1_b, qkv_b, qkvr);

    for (int blk = 0; blk < 2; blk++) {
        const uint4* wpb  = wpall + (size_t)blk * WP_BLK;
        const uint4* w2pb = w2p8  + (size_t)blk * W2P8_BLK;
        const float* rtin  = (blk == 0) ? rt : brt;
        const float* din   = (blk == 0) ? data : bd;
        float*       dout  = (blk == 0) ? bd : out_data;
        float*       rtout = (blk == 0) ? brt : out_rt;
        const int o1 = blk * NC, o3 = blk * 3 * NC, oh = blk * NHID;

        hot_block_kernel<<<NWIN, THREADS, SMEM_BYTES>>>(
            din, wpb, w2pb, rpef + (size_t)blk * RPEF_BLK,
            rpe + (size_t)blk * NH * SW * SW, qkvr, attn,
            cpe_w + blk * 3 * NC, cpe_b + o1, ln1_g + o1, ln1_b + o1,
            qkv_b + o3, proj_b + o1, ln2_g + o1, ln2_b + o1,
            b1 + oh, b2 + o1, gamma1 + o1, gamma2 + o1, dout);

        // post for this block; fuse next block's pre when blk == 0
        const uint4* wqkv_n = (blk == 0) ? (wpall + WP_BLK + WP_QKV) : nullptr;
        post_kernel<<<128, THREADS, POST_SMEM>>>(
            rtin, attn, wpb + WP_PROJ, wpb + WP_W1, wpb + WP_W2,
            proj_b + o1, ln2_g + o1, ln2_b + o1, b1 + oh, b2 + o1,
            gamma1 + o1, gamma2 + o1, rtout,
            wqkv_n, ln1_g + NC, ln1_b + NC, qkv_b + 3 * NC, qkvr);
    }
}